// round 5
// baseline (speedup 1.0000x reference)
#include <cuda_runtime.h>
#include <cuda_fp16.h>
#include <cstdint>
#include <cstddef>

// Problem constants
#define MB 8
#define TT 2048
#define CC 1024
#define MROWS (MB*TT)          // 16384
#define BTC (MROWS*CC)
#define BT4C (MROWS*4*CC)

// fp32 scratch (tf32-rounded where feeding GEMMs)
__device__ float g_h  [BTC];
__device__ float g_xk [BTC];
__device__ float g_xv [BTC];
__device__ float g_xr [BTC];
__device__ float g_k  [BTC];
__device__ float g_v  [BTC];
__device__ float g_r  [BTC];
__device__ float g_x2 [BTC];
__device__ float g_h2 [BTC];
__device__ float g_ck [BTC];
__device__ float g_cr [BTC];
__device__ float g_s  [BTC];
__device__ float g_kk [BT4C];
__device__ float g_wkvrT[3*CC*CC];   // wtkT | wtvT | wtrT  (K-major, tf32-rounded)
__device__ float g_wcksT[5*CC*CC];   // wckT | wcrT
__device__ float g_wcvT [4*CC*CC];   // wcvT

// ---------------------------------------------------------------------------
// Helpers
// ---------------------------------------------------------------------------
__device__ __forceinline__ uint32_t smem_u32(const void* p){
    uint32_t a;
    asm("{ .reg .u64 t; cvta.to.shared.u64 t, %1; cvt.u32.u64 %0, t; }" : "=r"(a) : "l"(p));
    return a;
}
__device__ __forceinline__ float rna_tf32(float v){
    asm("cvt.rna.tf32.f32 %0, %1;" : "=f"(v) : "f"(v));
    return v;
}
__device__ __forceinline__ void cp16(uint32_t dst, const void* src){
    asm volatile("cp.async.ca.shared.global [%0], [%1], 16;" :: "r"(dst), "l"(src));
}
#define CP_COMMIT() asm volatile("cp.async.commit_group;" ::: "memory")
#define CP_WAIT2()  asm volatile("cp.async.wait_group 2;" ::: "memory")
#define LDSM4(r0,r1,r2,r3,a) \
    asm volatile("ldmatrix.sync.aligned.m8n8.x4.shared.b16 {%0,%1,%2,%3}, [%4];" \
        : "=r"(r0),"=r"(r1),"=r"(r2),"=r"(r3) : "r"(a))

__device__ __forceinline__ void mma_tf32(float* d, const uint32_t* a, const uint32_t* b){
    asm volatile("mma.sync.aligned.m16n8k8.row.col.f32.tf32.tf32.f32 "
        "{%0,%1,%2,%3}, {%4,%5,%6,%7}, {%8,%9}, {%0,%1,%2,%3};"
        : "+f"(d[0]), "+f"(d[1]), "+f"(d[2]), "+f"(d[3])
        : "r"(a[0]), "r"(a[1]), "r"(a[2]), "r"(a[3]), "r"(b[0]), "r"(b[1]));
}

// ---------------------------------------------------------------------------
// LayerNorm: one 256-thread block per row of C=1024 (plain fp32 out)
// ---------------------------------------------------------------------------
__global__ void __launch_bounds__(256) ln_kernel(
    const float* __restrict__ x, const float* __restrict__ g,
    const float* __restrict__ b, float* __restrict__ out)
{
    const int C = CC;
    size_t row = blockIdx.x;
    const float4* xr = (const float4*)(x + row * C);
    int tid = threadIdx.x;
    float4 v = xr[tid];

    float s = v.x + v.y + v.z + v.w;
    #pragma unroll
    for (int o = 16; o > 0; o >>= 1) s += __shfl_xor_sync(0xffffffffu, s, o);
    __shared__ float ws[8];
    if ((tid & 31) == 0) ws[tid >> 5] = s;
    __syncthreads();
    float mu = (ws[0]+ws[1]+ws[2]+ws[3]+ws[4]+ws[5]+ws[6]+ws[7]) * (1.0f / C);
    __syncthreads();

    float dx = v.x - mu, dy = v.y - mu, dz = v.z - mu, dw = v.w - mu;
    float s2 = dx*dx + dy*dy + dz*dz + dw*dw;
    #pragma unroll
    for (int o = 16; o > 0; o >>= 1) s2 += __shfl_xor_sync(0xffffffffu, s2, o);
    if ((tid & 31) == 0) ws[tid >> 5] = s2;
    __syncthreads();
    float var = (ws[0]+ws[1]+ws[2]+ws[3]+ws[4]+ws[5]+ws[6]+ws[7]) * (1.0f / C);
    float rstd = rsqrtf(var + 1e-5f);

    float4 gv = ((const float4*)g)[tid];
    float4 bv = ((const float4*)b)[tid];
    float4 o;
    o.x = dx * rstd * gv.x + bv.x;
    o.y = dy * rstd * gv.y + bv.y;
    o.z = dz * rstd * gv.z + bv.z;
    o.w = dw * rstd * gv.w + bv.w;
    ((float4*)(out + row * C))[tid] = o;
}

// ---------------------------------------------------------------------------
// Token-shift mixes -> tf32-rounded fp32 operand arrays
// ---------------------------------------------------------------------------
__device__ __forceinline__ float4 mixf4r(float4 h, float4 hp, float4 m){
    float4 o;
    o.x = rna_tf32(h.x*m.x + hp.x*(1.f-m.x));
    o.y = rna_tf32(h.y*m.y + hp.y*(1.f-m.y));
    o.z = rna_tf32(h.z*m.z + hp.z*(1.f-m.z));
    o.w = rna_tf32(h.w*m.w + hp.w*(1.f-m.w));
    return o;
}
__global__ void __launch_bounds__(256) mix3_kernel(
    const float* __restrict__ h, const float* __restrict__ mk,
    const float* __restrict__ mv, const float* __restrict__ mr,
    float* xk, float* xv, float* xr)
{
    int j = blockIdx.x * 256 + threadIdx.x;   // float4 index
    int row = j >> 8;
    int c4  = j & 255;
    float4 hv = ((const float4*)h)[j];
    float4 hp = make_float4(0.f,0.f,0.f,0.f);
    if ((row & (TT-1)) != 0) hp = ((const float4*)h)[j - 256];
    ((float4*)xk)[j] = mixf4r(hv, hp, ((const float4*)mk)[c4]);
    ((float4*)xv)[j] = mixf4r(hv, hp, ((const float4*)mv)[c4]);
    ((float4*)xr)[j] = mixf4r(hv, hp, ((const float4*)mr)[c4]);
}
__global__ void __launch_bounds__(256) mix2_kernel(
    const float* __restrict__ h, const float* __restrict__ mk,
    const float* __restrict__ mr, float* ck, float* cr)
{
    int j = blockIdx.x * 256 + threadIdx.x;
    int row = j >> 8;
    int c4  = j & 255;
    float4 hv = ((const float4*)h)[j];
    float4 hp = make_float4(0.f,0.f,0.f,0.f);
    if ((row & (TT-1)) != 0) hp = ((const float4*)h)[j - 256];
    ((float4*)ck)[j] = mixf4r(hv, hp, ((const float4*)mk)[c4]);
    ((float4*)cr)[j] = mixf4r(hv, hp, ((const float4*)mr)[c4]);
}

// ---------------------------------------------------------------------------
// WKV sequential scan, fused x + r*y epilogue. 64 thr/block, 128 blocks.
// ---------------------------------------------------------------------------
__global__ void __launch_bounds__(64) wkv_kernel(
    const float* __restrict__ kp, const float* __restrict__ vp,
    const float* __restrict__ rp, const float* __restrict__ xp,
    const float* __restrict__ wdec, const float* __restrict__ ufst,
    float* __restrict__ out)
{
    int gid = blockIdx.x * 64 + threadIdx.x;   // 0..8191
    int b = gid >> 10;
    int c = gid & (CC - 1);
    float w = wdec[c], u = ufst[c];
    float aa = 0.0f, bb = 0.0f, pp = -1e38f;
    size_t idx = ((size_t)b * TT) * CC + c;
    #pragma unroll 2
    for (int t = 0; t < TT; t++, idx += CC) {
        float kk = kp[idx];
        float vv = vp[idx];
        float rr = rp[idx];
        float xx = xp[idx];
        float uk = u + kk;
        float p  = fmaxf(pp, uk);
        float e1 = __expf(pp - p);
        float e2 = __expf(uk - p);
        float y  = (e1 * aa + e2 * vv) / (e1 + e2);
        out[idx] = xx + rr * y;
        float pw = pp + w;
        float wk = w + kk;
        float p2 = fmaxf(pw, wk);
        float e1u = __expf(pw - p2);
        float e2u = __expf(wk - p2);
        aa = e1u * aa + e2u * vv;
        bb = e1u + e2u;
        pp = p2 + __logf(bb);
    }
}

// ---------------------------------------------------------------------------
// Weight transpose + tf32 RNA round: src[R,Ccols] fp32 -> dst[Ccols,R]
// ---------------------------------------------------------------------------
__global__ void __launch_bounds__(256) ttf32_kernel(
    const float* __restrict__ src, float* __restrict__ dst, int R, int Ccols)
{
    __shared__ float t[32][33];
    int r0 = blockIdx.y * 32, c0 = blockIdx.x * 32;
    int tx = threadIdx.x, ty = threadIdx.y;
    #pragma unroll
    for (int j = 0; j < 32; j += 8)
        t[ty + j][tx] = src[(size_t)(r0 + ty + j) * Ccols + c0 + tx];
    __syncthreads();
    #pragma unroll
    for (int j = 0; j < 32; j += 8)
        dst[(size_t)(c0 + ty + j) * R + r0 + tx] = rna_tf32(t[tx][ty + j]);
}

// ---------------------------------------------------------------------------
// tf32 GEMM core with ldmatrix fragment loads.
// C[M,N] = epi(A[M,K] @ Bt[N,K]^T), operands fp32 (tf32-rounded).
// CTA tile 256x128, BK=16, 4-stage cp.async pipeline, warps 4x2, 64x64 each.
// Smem layout per operand: 8-row blocks; phys(row,c)= (row>>3)*512 + c*128
//   + (row&7)*16, c = 16B chunk (4 tf32) index 0..3.
// ---------------------------------------------------------------------------
#define CTM 256
#define CTN 128
#define ST_A 16384
#define ST_B 8192
#define STAGE_BYTES 24576
#define GSMEM (STAGE_BYTES*4)   // 98304

#define EPI_NONE 0
#define EPI_SIGMOID 1
#define EPI_RELUSQ 2
#define EPI_RESID 3

template<int EPI>
__device__ __forceinline__ void gemm_core(
    const float* __restrict__ A, const float* __restrict__ Bt,
    int K, int m0, int n0B,
    float* __restrict__ outF, const float* __restrict__ resid,
    const float* __restrict__ gate, int Nout, int n0o)
{
    extern __shared__ char smem[];
    const uint32_t sbase = smem_u32(smem);
    const int tid = threadIdx.x;
    const int lane = tid & 31, wid = tid >> 5;
    const int wm = wid & 3, wn = wid >> 2;
    const int NS = K >> 4;

    auto load_stage = [&](int s, int buf){
        const int k0 = s << 4;
        uint32_t st = sbase + (uint32_t)buf * STAGE_BYTES;
        #pragma unroll
        for (int l = 0; l < 4; l++) {
            int chk = l*256 + tid;                 // 0..1023 (256 rows x 4 chunks)
            int row = chk >> 2, c = chk & 3;
            uint32_t d = (uint32_t)((row>>3)*512 + c*128 + (row&7)*16);
            cp16(st + d, A + (size_t)(m0+row)*K + k0 + c*4);
        }
        #pragma unroll
        for (int l = 0; l < 2; l++) {
            int chk = l*256 + tid;                 // 0..511 (128 rows x 4 chunks)
            int row = chk >> 2, c = chk & 3;
            uint32_t d = (uint32_t)((row>>3)*512 + c*128 + (row&7)*16);
            cp16(st + ST_A + d, Bt + (size_t)(n0B+row)*K + k0 + c*4);
        }
    };

    float acc[4][8][4];
    #pragma unroll
    for (int mi = 0; mi < 4; mi++)
        #pragma unroll
        for (int ni = 0; ni < 8; ni++)
            #pragma unroll
            for (int c = 0; c < 4; c++) acc[mi][ni][c] = 0.0f;

    load_stage(0, 0); CP_COMMIT();
    load_stage(1, 1); CP_COMMIT();
    load_stage(2, 2); CP_COMMIT();

    // ldmatrix per-lane address parts (see header comment for phys()):
    // A x4: mats = {rows 0-7 c0, rows 8-15 c0, rows 0-7 c0+1, rows 8-15 c0+1}
    const uint32_t laneA = (uint32_t)(((lane>>3)&1)*512 + (lane>>4)*128 + (lane&7)*16);
    // B x4: mats = {n 0-7 c0, n 0-7 c0+1, n 8-15 c0, n 8-15 c0+1}
    const uint32_t laneB = (uint32_t)((lane>>4)*512 + ((lane>>3)&1)*128 + (lane&7)*16);

    for (int s = 0; s < NS; s++) {
        int buf = s & 3;
        CP_WAIT2();
        __syncthreads();
        if (s + 3 < NS) load_stage(s + 3, (s + 3) & 3);
        CP_COMMIT();

        uint32_t stA = sbase + (uint32_t)buf * STAGE_BYTES;
        uint32_t stB = stA + ST_A;

        #pragma unroll
        for (int ks = 0; ks < 2; ks++) {
            uint32_t a[4][4], b[8][2];
            #pragma unroll
            for (int mi = 0; mi < 4; mi++) {
                uint32_t ad = stA + (uint32_t)((wm*8 + mi*2)*512 + ks*256) + laneA;
                LDSM4(a[mi][0], a[mi][1], a[mi][2], a[mi][3], ad);
            }
            #pragma unroll
            for (int g = 0; g < 4; g++) {
                uint32_t bd = stB + (uint32_t)((wn*8 + g*2)*512 + ks*256) + laneB;
                uint32_t r0, r1, r2, r3;
                LDSM4(r0, r1, r2, r3, bd);
                b[2*g][0] = r0;   b[2*g][1] = r1;
                b[2*g+1][0] = r2; b[2*g+1][1] = r3;
            }
            #pragma unroll
            for (int mi = 0; mi < 4; mi++)
                #pragma unroll
                for (int ni = 0; ni < 8; ni++)
                    mma_tf32(acc[mi][ni], a[mi], b[ni]);
        }
    }

    // ---- epilogue
    #pragma unroll
    for (int mi = 0; mi < 4; mi++) {
        int r0 = m0 + wm*64 + mi*16 + (lane >> 2);
        #pragma unroll
        for (int ni = 0; ni < 8; ni++) {
            int c0 = n0o + wn*64 + ni*8 + (lane & 3)*2;
            float v0 = acc[mi][ni][0], v1 = acc[mi][ni][1];
            float v2 = acc[mi][ni][2], v3 = acc[mi][ni][3];
            size_t i0 = (size_t)r0 * Nout + c0;
            size_t i1 = (size_t)(r0 + 8) * Nout + c0;
            if (EPI == EPI_SIGMOID) {
                v0 = 1.f/(1.f+__expf(-v0)); v1 = 1.f/(1.f+__expf(-v1));
                v2 = 1.f/(1.f+__expf(-v2)); v3 = 1.f/(1.f+__expf(-v3));
            } else if (EPI == EPI_RELUSQ) {
                v0 = fmaxf(v0,0.f); v1 = fmaxf(v1,0.f);
                v2 = fmaxf(v2,0.f); v3 = fmaxf(v3,0.f);
                v0 = rna_tf32(v0*v0); v1 = rna_tf32(v1*v1);
                v2 = rna_tf32(v2*v2); v3 = rna_tf32(v3*v3);
            } else if (EPI == EPI_RESID) {
                float2 rz0 = *(const float2*)(resid + i0);
                float2 rz1 = *(const float2*)(resid + i1);
                float2 gz0 = *(const float2*)(gate  + i0);
                float2 gz1 = *(const float2*)(gate  + i1);
                v0 = rz0.x + gz0.x*v0; v1 = rz0.y + gz0.y*v1;
                v2 = rz1.x + gz1.x*v2; v3 = rz1.y + gz1.y*v3;
            }
            *(float2*)(outF + i0) = make_float2(v0, v1);
            *(float2*)(outF + i1) = make_float2(v2, v3);
        }
    }
}

// Fused k|v|r GEMM: N-blocks 0-7 -> k, 8-15 -> v, 16-23 -> sigmoid r
__global__ void __launch_bounds__(256, 1) gemm_kvr(
    const float* xk, const float* xv, const float* xr,
    const float* Bt, float* outk, float* outv, float* outr)
{
    int seg = blockIdx.x >> 3;
    int m0  = blockIdx.y * CTM;
    int n0B = blockIdx.x * CTN;
    int n0o = (blockIdx.x & 7) * CTN;
    const float* Aa = (seg == 0) ? xk : (seg == 1) ? xv : xr;
    float* o = (seg == 0) ? outk : (seg == 1) ? outv : outr;
    if (seg == 2)
        gemm_core<EPI_SIGMOID>(Aa, Bt, CC, m0, n0B, o, nullptr, nullptr, CC, n0o);
    else
        gemm_core<EPI_NONE>(Aa, Bt, CC, m0, n0B, o, nullptr, nullptr, CC, n0o);
}

// Fused kk|s GEMM: N-blocks 0-31 -> relu^2 kk (tf32-rounded), 32-39 -> sigmoid s
__global__ void __launch_bounds__(256, 1) gemm_cks(
    const float* ck, const float* cr, const float* Bt,
    float* kk, float* outs)
{
    int bx = blockIdx.x;
    int m0 = blockIdx.y * CTM;
    int n0B = bx * CTN;
    if (bx < 32)
        gemm_core<EPI_RELUSQ>(ck, Bt, CC, m0, n0B, kk, nullptr, nullptr, 4*CC, bx*CTN);
    else
        gemm_core<EPI_SIGMOID>(cr, Bt, CC, m0, n0B, outs, nullptr, nullptr, CC, (bx-32)*CTN);
}

// Final GEMM: out = x2 + s * (kk @ w_cv), K = 4096
__global__ void __launch_bounds__(256, 1) gemm_out(
    const float* kk, const float* Bt,
    float* out, const float* x2, const float* sg)
{
    int m0 = blockIdx.y * CTM;
    int n0 = blockIdx.x * CTN;
    gemm_core<EPI_RESID>(kk, Bt, 4*CC, m0, n0, out, x2, sg, CC, n0);
}

// ---------------------------------------------------------------------------
// Host launcher
// ---------------------------------------------------------------------------
template<typename T>
static T* symaddr(const void* sym)
{
    void* p = nullptr;
    cudaGetSymbolAddress(&p, sym);
    return (T*)p;
}

extern "C" void kernel_launch(void* const* d_in, const int* in_sizes, int n_in,
                              void* d_out, int out_size)
{
    const float* x      = (const float*)d_in[0];
    const float* tdecay = (const float*)d_in[1];
    const float* tfirst = (const float*)d_in[2];
    const float* w_tk   = (const float*)d_in[3];
    const float* w_tv   = (const float*)d_in[4];
    const float* w_tr   = (const float*)d_in[5];
    const float* w_ck   = (const float*)d_in[6];
    const float* w_cv   = (const float*)d_in[7];
    const float* w_cr   = (const float*)d_in[8];
    const float* ln1_g  = (const float*)d_in[9];
    const float* ln1_b  = (const float*)d_in[10];
    const float* ln2_g  = (const float*)d_in[11];
    const float* ln2_b  = (const float*)d_in[12];
    const float* mix_k  = (const float*)d_in[13];
    const float* mix_v  = (const float*)d_in[14];
    const float* mix_r  = (const float*)d_in[15];
    const float* cmix_k = (const float*)d_in[16];
    const float* cmix_r = (const float*)d_in[17];
    float* out = (float*)d_out;

    float* h    = symaddr<float>(g_h);
    float* xk   = symaddr<float>(g_xk);
    float* xv   = symaddr<float>(g_xv);
    float* xr   = symaddr<float>(g_xr);
    float* k    = symaddr<float>(g_k);
    float* v    = symaddr<float>(g_v);
    float* r    = symaddr<float>(g_r);
    float* x2   = symaddr<float>(g_x2);
    float* h2   = symaddr<float>(g_h2);
    float* ck   = symaddr<float>(g_ck);
    float* cr   = symaddr<float>(g_cr);
    float* s    = symaddr<float>(g_s);
    float* kk   = symaddr<float>(g_kk);
    float* wkvrT = symaddr<float>(g_wkvrT);
    float* wcksT = symaddr<float>(g_wcksT);
    float* wcvT  = symaddr<float>(g_wcvT);

    cudaFuncSetAttribute((const void*)gemm_kvr, cudaFuncAttributeMaxDynamicSharedMemorySize, GSMEM);
    cudaFuncSetAttribute((const void*)gemm_cks, cudaFuncAttributeMaxDynamicSharedMemorySize, GSMEM);
    cudaFuncSetAttribute((const void*)gemm_out, cudaFuncAttributeMaxDynamicSharedMemorySize, GSMEM);

    const int M = MROWS;
    dim3 tb(32, 8);
    const int mixg = (BTC/4) / 256;

    // 0-2) transpose+round time-mix weights into concat buffer [3072,1024]
    ttf32_kernel<<<dim3(CC/32, CC/32), tb>>>(w_tk, wkvrT,           CC, CC);
    ttf32_kernel<<<dim3(CC/32, CC/32), tb>>>(w_tv, wkvrT + CC*CC,   CC, CC);
    ttf32_kernel<<<dim3(CC/32, CC/32), tb>>>(w_tr, wkvrT + 2*CC*CC, CC, CC);

    // 3) h = LN1(x);  4) token-shift mixes (tf32-rounded)
    ln_kernel<<<M, 256>>>(x, ln1_g, ln1_b, h);
    mix3_kernel<<<mixg, 256>>>(h, mix_k, mix_v, mix_r, xk, xv, xr);

    // 5) fused k|v|r GEMM  (launch idx 5 -> ncu capture target)
    gemm_kvr<<<dim3(24, M/CTM), 256, GSMEM>>>(xk, xv, xr, wkvrT, k, v, r);

    // 6) x2 = x + r * WKV(k, v)
    wkv_kernel<<<128, 64>>>(k, v, r, x, tdecay, tfirst, x2);

    // 7) h2 = LN2(x2);  8) channel mixes
    ln_kernel<<<M, 256>>>(x2, ln2_g, ln2_b, h2);
    mix2_kernel<<<mixg, 256>>>(h2, cmix_k, cmix_r, ck, cr);

    // 9-11) transpose+round channel weights: concat [5120,1024] and [1024,4096]
    ttf32_kernel<<<dim3(4*CC/32, CC/32), tb>>>(w_ck, wcksT,           CC, 4*CC);
    ttf32_kernel<<<dim3(CC/32, CC/32),   tb>>>(w_cr, wcksT + 4*CC*CC, CC, CC);
    ttf32_kernel<<<dim3(CC/32, 4*CC/32), tb>>>(w_cv, wcvT,            4*CC, CC);

    // 12) fused kk|s GEMM: kk = relu(ck@w_ck)^2 (tf32-rounded), s = sigmoid(cr@w_cr)
    gemm_cks<<<dim3(40, M/CTM), 256, GSMEM>>>(ck, cr, wcksT, kk, s);

    // 13) out = x2 + s * (kk @ w_cv), K = 4096
    gemm_out<<<dim3(8, M/CTM), 256, GSMEM>>>(kk, wcvT, out, x2, s);
}

// round 7
// speedup vs baseline: 1.5043x; 1.5043x over previous
#include <cuda_runtime.h>
#include <cstdint>
#include <cstddef>

// Problem constants
#define MB 8
#define TT 2048
#define CC 1024
#define MROWS (MB*TT)          // 16384
#define BTC (MROWS*CC)
#define BT4C (MROWS*4*CC)

// fp32 scratch (tf32-RNA-rounded where feeding GEMMs)
__device__ float g_h  [BTC];
__device__ float g_xk [BTC];
__device__ float g_xv [BTC];
__device__ float g_xr [BTC];
__device__ float g_k  [BTC];
__device__ float g_v  [BTC];
__device__ float g_r  [BTC];
__device__ float g_x2 [BTC];
__device__ float g_h2 [BTC];
__device__ float g_ck [BTC];
__device__ float g_cr [BTC];
__device__ float g_s  [BTC];
__device__ float g_kk [BT4C];
__device__ float g_wtkT[CC*CC];
__device__ float g_wtvT[CC*CC];
__device__ float g_wtrT[CC*CC];
__device__ float g_wcrT[CC*CC];
__device__ float g_wckT[4*CC*CC];
__device__ float g_wcvT[4*CC*CC];

// ---------------------------------------------------------------------------
// Helpers
// ---------------------------------------------------------------------------
__device__ __forceinline__ uint32_t smem_u32(const void* p){
    uint32_t a;
    asm("{ .reg .u64 t; cvta.to.shared.u64 t, %1; cvt.u32.u64 %0, t; }" : "=r"(a) : "l"(p));
    return a;
}
__device__ __forceinline__ float rna_tf32(float v){
    asm("cvt.rna.tf32.f32 %0, %1;" : "=f"(v) : "f"(v));
    return v;
}
__device__ __forceinline__ void cp16(uint32_t dst, const void* src){
    asm volatile("cp.async.ca.shared.global [%0], [%1], 16;" :: "r"(dst), "l"(src));
}
#define CP_COMMIT() asm volatile("cp.async.commit_group;" ::: "memory")
#define CP_WAIT2()  asm volatile("cp.async.wait_group 2;" ::: "memory")

__device__ __forceinline__ void mma_tf32(float* d, const uint32_t* a, const uint32_t* b){
    asm volatile("mma.sync.aligned.m16n8k8.row.col.f32.tf32.tf32.f32 "
        "{%0,%1,%2,%3}, {%4,%5,%6,%7}, {%8,%9}, {%0,%1,%2,%3};"
        : "+f"(d[0]), "+f"(d[1]), "+f"(d[2]), "+f"(d[3])
        : "r"(a[0]), "r"(a[1]), "r"(a[2]), "r"(a[3]), "r"(b[0]), "r"(b[1]));
}
__device__ __forceinline__ uint32_t lds32(uint32_t addr){
    uint32_t v;
    asm volatile("ld.shared.b32 %0, [%1];" : "=r"(v) : "r"(addr));
    return v;
}

// ---------------------------------------------------------------------------
// LayerNorm: one 256-thread block per row of C=1024
// ---------------------------------------------------------------------------
__global__ void __launch_bounds__(256) ln_kernel(
    const float* __restrict__ x, const float* __restrict__ g,
    const float* __restrict__ b, float* __restrict__ out)
{
    const int C = CC;
    size_t row = blockIdx.x;
    const float4* xr = (const float4*)(x + row * C);
    int tid = threadIdx.x;
    float4 v = xr[tid];

    float s = v.x + v.y + v.z + v.w;
    #pragma unroll
    for (int o = 16; o > 0; o >>= 1) s += __shfl_xor_sync(0xffffffffu, s, o);
    __shared__ float ws[8];
    if ((tid & 31) == 0) ws[tid >> 5] = s;
    __syncthreads();
    float mu = (ws[0]+ws[1]+ws[2]+ws[3]+ws[4]+ws[5]+ws[6]+ws[7]) * (1.0f / C);
    __syncthreads();

    float dx = v.x - mu, dy = v.y - mu, dz = v.z - mu, dw = v.w - mu;
    float s2 = dx*dx + dy*dy + dz*dz + dw*dw;
    #pragma unroll
    for (int o = 16; o > 0; o >>= 1) s2 += __shfl_xor_sync(0xffffffffu, s2, o);
    if ((tid & 31) == 0) ws[tid >> 5] = s2;
    __syncthreads();
    float var = (ws[0]+ws[1]+ws[2]+ws[3]+ws[4]+ws[5]+ws[6]+ws[7]) * (1.0f / C);
    float rstd = rsqrtf(var + 1e-5f);

    float4 gv = ((const float4*)g)[tid];
    float4 bv = ((const float4*)b)[tid];
    float4 o;
    o.x = dx * rstd * gv.x + bv.x;
    o.y = dy * rstd * gv.y + bv.y;
    o.z = dz * rstd * gv.z + bv.z;
    o.w = dw * rstd * gv.w + bv.w;
    ((float4*)(out + row * C))[tid] = o;
}

// ---------------------------------------------------------------------------
// Token-shift mixes -> tf32-RNA-rounded fp32 operand arrays
// ---------------------------------------------------------------------------
__device__ __forceinline__ float4 mixf4r(float4 h, float4 hp, float4 m){
    float4 o;
    o.x = rna_tf32(h.x*m.x + hp.x*(1.f-m.x));
    o.y = rna_tf32(h.y*m.y + hp.y*(1.f-m.y));
    o.z = rna_tf32(h.z*m.z + hp.z*(1.f-m.z));
    o.w = rna_tf32(h.w*m.w + hp.w*(1.f-m.w));
    return o;
}
__global__ void __launch_bounds__(256) mix3_kernel(
    const float* __restrict__ h, const float* __restrict__ mk,
    const float* __restrict__ mv, const float* __restrict__ mr,
    float* xk, float* xv, float* xr)
{
    int j = blockIdx.x * 256 + threadIdx.x;   // float4 index
    int row = j >> 8;
    int c4  = j & 255;
    float4 hv = ((const float4*)h)[j];
    float4 hp = make_float4(0.f,0.f,0.f,0.f);
    if ((row & (TT-1)) != 0) hp = ((const float4*)h)[j - 256];
    ((float4*)xk)[j] = mixf4r(hv, hp, ((const float4*)mk)[c4]);
    ((float4*)xv)[j] = mixf4r(hv, hp, ((const float4*)mv)[c4]);
    ((float4*)xr)[j] = mixf4r(hv, hp, ((const float4*)mr)[c4]);
}
__global__ void __launch_bounds__(256) mix2_kernel(
    const float* __restrict__ h, const float* __restrict__ mk,
    const float* __restrict__ mr, float* ck, float* cr)
{
    int j = blockIdx.x * 256 + threadIdx.x;
    int row = j >> 8;
    int c4  = j & 255;
    float4 hv = ((const float4*)h)[j];
    float4 hp = make_float4(0.f,0.f,0.f,0.f);
    if ((row & (TT-1)) != 0) hp = ((const float4*)h)[j - 256];
    ((float4*)ck)[j] = mixf4r(hv, hp, ((const float4*)mk)[c4]);
    ((float4*)cr)[j] = mixf4r(hv, hp, ((const float4*)mr)[c4]);
}

// ---------------------------------------------------------------------------
// WKV sequential scan, fused x + r*y epilogue. 64 thr/block, 128 blocks.
// ---------------------------------------------------------------------------
__global__ void __launch_bounds__(64) wkv_kernel(
    const float* __restrict__ kp, const float* __restrict__ vp,
    const float* __restrict__ rp, const float* __restrict__ xp,
    const float* __restrict__ wdec, const float* __restrict__ ufst,
    float* __restrict__ out)
{
    int gid = blockIdx.x * 64 + threadIdx.x;   // 0..8191
    int b = gid >> 10;
    int c = gid & (CC - 1);
    float w = wdec[c], u = ufst[c];
    float aa = 0.0f, bb = 0.0f, pp = -1e38f;
    size_t idx = ((size_t)b * TT) * CC + c;
    #pragma unroll 2
    for (int t = 0; t < TT; t++, idx += CC) {
        float kk = kp[idx];
        float vv = vp[idx];
        float rr = rp[idx];
        float xx = xp[idx];
        float uk = u + kk;
        float p  = fmaxf(pp, uk);
        float e1 = __expf(pp - p);
        float e2 = __expf(uk - p);
        float y  = (e1 * aa + e2 * vv) / (e1 + e2);
        out[idx] = xx + rr * y;
        float pw = pp + w;
        float wk = w + kk;
        float p2 = fmaxf(pw, wk);
        float e1u = __expf(pw - p2);
        float e2u = __expf(wk - p2);
        aa = e1u * aa + e2u * vv;
        bb = e1u + e2u;
        pp = p2 + __logf(bb);
    }
}

// ---------------------------------------------------------------------------
// Weight transpose + tf32 RNA round: src[R,Ccols] fp32 -> dst[Ccols,R]
// ---------------------------------------------------------------------------
__global__ void __launch_bounds__(256) ttf32_kernel(
    const float* __restrict__ src, float* __restrict__ dst, int R, int Ccols)
{
    __shared__ float t[32][33];
    int r0 = blockIdx.y * 32, c0 = blockIdx.x * 32;
    int tx = threadIdx.x, ty = threadIdx.y;
    #pragma unroll
    for (int j = 0; j < 32; j += 8)
        t[ty + j][tx] = src[(size_t)(r0 + ty + j) * Ccols + c0 + tx];
    __syncthreads();
    #pragma unroll
    for (int j = 0; j < 32; j += 8)
        dst[(size_t)(c0 + ty + j) * R + r0 + tx] = rna_tf32(t[tx][ty + j]);
}

// ---------------------------------------------------------------------------
// tf32 mma.sync GEMM (R3 design, re-tiled for occupancy):
// C[M,N] = epi(A[M,K] @ Bt[N,K]^T), operands fp32 (tf32-rounded).
// CTA 256x128 tile, 512 threads (16 warps, 4x4 grid), warp tile 64x32.
// BK=16, 4-stage cp.async pipeline, R3's XOR-swizzled smem + scalar LDS frags.
// ---------------------------------------------------------------------------
#define CTM 256
#define CTN 128
#define GBK 16
#define A_BYTES (CTM*GBK*4)              // 16384
#define B_BYTES (CTN*GBK*4)              // 8192
#define STAGE_BYTES (A_BYTES + B_BYTES)  // 24576
#define GSMEM (STAGE_BYTES*4)            // 98304
#define NTHR 512

#define EPI_NONE 0
#define EPI_SIGMOID 1
#define EPI_RELUSQ 2
#define EPI_RESID 3

template<int EPI>
__global__ void __launch_bounds__(NTHR, 1) mma_gemm(
    const float* __restrict__ A, const float* __restrict__ Bt,
    float* __restrict__ Cc,
    const float* __restrict__ resid, const float* __restrict__ gate,
    int M, int N, int K)
{
    extern __shared__ char smem[];
    const uint32_t sbase = smem_u32(smem);
    const int tid = threadIdx.x;
    const int lane = tid & 31, wid = tid >> 5;
    const int wm = wid & 3, wn = wid >> 2;           // 4x4 warp grid
    const int m0 = blockIdx.y * CTM, n0 = blockIdx.x * CTN;
    const int NS = K / GBK;

    // stage loader (cp.async, R3 swizzle: chunk k4 -> k4 ^ ((row>>1)&3))
    auto load_stage = [&](int s, int buf){
        const int k0 = s * GBK;
        uint32_t sA = sbase + (uint32_t)buf * STAGE_BYTES;
        uint32_t sB = sA + A_BYTES;
        #pragma unroll
        for (int l = 0; l < 2; l++) {
            int j = l*NTHR + tid;                // 0..1023 float4s of A tile
            int row = j >> 2, k4 = j & 3;
            const float* src = A + (size_t)(m0 + row) * K + k0 + k4*4;
            uint32_t dst = sA + (uint32_t)(row*64) + (uint32_t)((k4 ^ ((row>>1)&3)) * 16);
            cp16(dst, src);
        }
        {
            int j = tid;                          // 0..511 float4s of B tile
            int row = j >> 2, k4 = j & 3;
            const float* src = Bt + (size_t)(n0 + row) * K + k0 + k4*4;
            uint32_t dst = sB + (uint32_t)(row*64) + (uint32_t)((k4 ^ ((row>>1)&3)) * 16);
            cp16(dst, src);
        }
    };

    float acc[4][4][4];
    #pragma unroll
    for (int mi = 0; mi < 4; mi++)
        #pragma unroll
        for (int ni = 0; ni < 4; ni++)
            #pragma unroll
            for (int c = 0; c < 4; c++) acc[mi][ni][c] = 0.0f;

    load_stage(0, 0); CP_COMMIT();
    load_stage(1, 1); CP_COMMIT();
    load_stage(2, 2); CP_COMMIT();

    const int q    = (lane >> 3) & 3;
    const int colk = lane & 3;
    const uint32_t a_row_off = (uint32_t)((wm*64 + (lane>>2)) * 64);  // bytes
    const uint32_t b_row_off = (uint32_t)((wn*32 + (lane>>2)) * 64);

    for (int s = 0; s < NS; s++) {
        int buf = s & 3;
        CP_WAIT2();
        __syncthreads();
        if (s + 3 < NS) { load_stage(s + 3, (s + 3) & 3); }
        CP_COMMIT();

        uint32_t sA = sbase + (uint32_t)buf * STAGE_BYTES;
        uint32_t sB = sA + A_BYTES;
        #pragma unroll
        for (int ks = 0; ks < 2; ks++) {
            uint32_t ka0 = (uint32_t)((colk + 4*((2*ks + 0) ^ q)) * 4);
            uint32_t ka1 = (uint32_t)((colk + 4*((2*ks + 1) ^ q)) * 4);
            uint32_t a[4][4];
            #pragma unroll
            for (int mi = 0; mi < 4; mi++) {
                uint32_t base = sA + a_row_off + (uint32_t)(mi * 16 * 64);
                a[mi][0] = lds32(base + ka0);
                a[mi][1] = lds32(base + 8*64 + ka0);
                a[mi][2] = lds32(base + ka1);
                a[mi][3] = lds32(base + 8*64 + ka1);
            }
            uint32_t b[4][2];
            #pragma unroll
            for (int ni = 0; ni < 4; ni++) {
                uint32_t base = sB + b_row_off + (uint32_t)(ni * 8 * 64);
                b[ni][0] = lds32(base + ka0);
                b[ni][1] = lds32(base + ka1);
            }
            #pragma unroll
            for (int mi = 0; mi < 4; mi++)
                #pragma unroll
                for (int ni = 0; ni < 4; ni++)
                    mma_tf32(acc[mi][ni], a[mi], b[ni]);
        }
        __syncthreads();
    }

    // ---- epilogue: registers -> global, fused ops
    #pragma unroll
    for (int mi = 0; mi < 4; mi++) {
        int r0 = m0 + wm*64 + mi*16 + (lane >> 2);
        #pragma unroll
        for (int ni = 0; ni < 4; ni++) {
            int c0 = n0 + wn*32 + ni*8 + (lane & 3)*2;
            float v0 = acc[mi][ni][0], v1 = acc[mi][ni][1];
            float v2 = acc[mi][ni][2], v3 = acc[mi][ni][3];
            if (EPI == EPI_SIGMOID) {
                v0 = 1.f/(1.f+__expf(-v0)); v1 = 1.f/(1.f+__expf(-v1));
                v2 = 1.f/(1.f+__expf(-v2)); v3 = 1.f/(1.f+__expf(-v3));
            } else if (EPI == EPI_RELUSQ) {
                v0 = fmaxf(v0,0.f); v1 = fmaxf(v1,0.f);
                v2 = fmaxf(v2,0.f); v3 = fmaxf(v3,0.f);
                v0 = rna_tf32(v0*v0); v1 = rna_tf32(v1*v1);
                v2 = rna_tf32(v2*v2); v3 = rna_tf32(v3*v3);
            }
            size_t i0 = (size_t)r0 * N + c0;
            size_t i1 = (size_t)(r0 + 8) * N + c0;
            if (EPI == EPI_RESID) {
                float2 rz0 = *(const float2*)(resid + i0);
                float2 rz1 = *(const float2*)(resid + i1);
                float2 gz0 = *(const float2*)(gate  + i0);
                float2 gz1 = *(const float2*)(gate  + i1);
                v0 = rz0.x + gz0.x*v0; v1 = rz0.y + gz0.y*v1;
                v2 = rz1.x + gz1.x*v2; v3 = rz1.y + gz1.y*v3;
            }
            *(float2*)(Cc + i0) = make_float2(v0, v1);
            *(float2*)(Cc + i1) = make_float2(v2, v3);
        }
    }
}

// ---------------------------------------------------------------------------
// Host launcher
// ---------------------------------------------------------------------------
template<typename T>
static T* symaddr(const void* sym)
{
    void* p = nullptr;
    cudaGetSymbolAddress(&p, sym);
    return (T*)p;
}

extern "C" void kernel_launch(void* const* d_in, const int* in_sizes, int n_in,
                              void* d_out, int out_size)
{
    const float* x      = (const float*)d_in[0];
    const float* tdecay = (const float*)d_in[1];
    const float* tfirst = (const float*)d_in[2];
    const float* w_tk   = (const float*)d_in[3];
    const float* w_tv   = (const float*)d_in[4];
    const float* w_tr   = (const float*)d_in[5];
    const float* w_ck   = (const float*)d_in[6];
    const float* w_cv   = (const float*)d_in[7];
    const float* w_cr   = (const float*)d_in[8];
    const float* ln1_g  = (const float*)d_in[9];
    const float* ln1_b  = (const float*)d_in[10];
    const float* ln2_g  = (const float*)d_in[11];
    const float* ln2_b  = (const float*)d_in[12];
    const float* mix_k  = (const float*)d_in[13];
    const float* mix_v  = (const float*)d_in[14];
    const float* mix_r  = (const float*)d_in[15];
    const float* cmix_k = (const float*)d_in[16];
    const float* cmix_r = (const float*)d_in[17];
    float* out = (float*)d_out;

    float* h    = symaddr<float>(g_h);
    float* xk   = symaddr<float>(g_xk);
    float* xv   = symaddr<float>(g_xv);
    float* xr   = symaddr<float>(g_xr);
    float* k    = symaddr<float>(g_k);
    float* v    = symaddr<float>(g_v);
    float* r    = symaddr<float>(g_r);
    float* x2   = symaddr<float>(g_x2);
    float* h2   = symaddr<float>(g_h2);
    float* ck   = symaddr<float>(g_ck);
    float* cr   = symaddr<float>(g_cr);
    float* s    = symaddr<float>(g_s);
    float* kk   = symaddr<float>(g_kk);
    float* wtkT = symaddr<float>(g_wtkT);
    float* wtvT = symaddr<float>(g_wtvT);
    float* wtrT = symaddr<float>(g_wtrT);
    float* wcrT = symaddr<float>(g_wcrT);
    float* wckT = symaddr<float>(g_wckT);
    float* wcvT = symaddr<float>(g_wcvT);

    cudaFuncSetAttribute((const void*)mma_gemm<EPI_NONE>,    cudaFuncAttributeMaxDynamicSharedMemorySize, GSMEM);
    cudaFuncSetAttribute((const void*)mma_gemm<EPI_SIGMOID>, cudaFuncAttributeMaxDynamicSharedMemorySize, GSMEM);
    cudaFuncSetAttribute((const void*)mma_gemm<EPI_RELUSQ>,  cudaFuncAttributeMaxDynamicSharedMemorySize, GSMEM);
    cudaFuncSetAttribute((const void*)mma_gemm<EPI_RESID>,   cudaFuncAttributeMaxDynamicSharedMemorySize, GSMEM);

    const int M = MROWS;
    dim3 tb(32, 8);
    const int mixg = (BTC/4) / 256;

    // 0) transpose + RNA-round weights -> K-major B operands
    ttf32_kernel<<<dim3(CC/32,   CC/32),   tb>>>(w_tk, wtkT, CC,   CC);
    ttf32_kernel<<<dim3(CC/32,   CC/32),   tb>>>(w_tv, wtvT, CC,   CC);
    ttf32_kernel<<<dim3(CC/32,   CC/32),   tb>>>(w_tr, wtrT, CC,   CC);
    ttf32_kernel<<<dim3(CC/32,   CC/32),   tb>>>(w_cr, wcrT, CC,   CC);
    ttf32_kernel<<<dim3(4*CC/32, CC/32),   tb>>>(w_ck, wckT, CC,   4*CC);
    ttf32_kernel<<<dim3(CC/32,   4*CC/32), tb>>>(w_cv, wcvT, 4*CC, CC);

    dim3 gC (CC/CTN,   M/CTM);    // (8, 64)
    dim3 g4C(4*CC/CTN, M/CTM);    // (32, 64)

    // 1) h = LN1(x)
    ln_kernel<<<M, 256>>>(x, ln1_g, ln1_b, h);

    // 2) token-shift mixes (tf32-rounded)
    mix3_kernel<<<mixg, 256>>>(h, mix_k, mix_v, mix_r, xk, xv, xr);

    // 3) k, v, r GEMMs (r with sigmoid)
    mma_gemm<EPI_NONE>   <<<gC, NTHR, GSMEM>>>(xk, wtkT, k, nullptr, nullptr, M, CC, CC);
    mma_gemm<EPI_NONE>   <<<gC, NTHR, GSMEM>>>(xv, wtvT, v, nullptr, nullptr, M, CC, CC);
    mma_gemm<EPI_SIGMOID><<<gC, NTHR, GSMEM>>>(xr, wtrT, r, nullptr, nullptr, M, CC, CC);

    // 4) x2 = x + r * WKV(k, v)
    wkv_kernel<<<128, 64>>>(k, v, r, x, tdecay, tfirst, x2);

    // 5) h2 = LN2(x2)
    ln_kernel<<<M, 256>>>(x2, ln2_g, ln2_b, h2);

    // 6) channel-mix shifts (tf32-rounded)
    mix2_kernel<<<mixg, 256>>>(h2, cmix_k, cmix_r, ck, cr);

    // 7) kk = relu(ck @ w_ck)^2   [M, 4096]  (tf32-rounded output)
    mma_gemm<EPI_RELUSQ> <<<g4C, NTHR, GSMEM>>>(ck, wckT, kk, nullptr, nullptr, M, 4*CC, CC);

    // 8) s = sigmoid(cr @ w_cr)
    mma_gemm<EPI_SIGMOID><<<gC, NTHR, GSMEM>>>(cr, wcrT, s, nullptr, nullptr, M, CC, CC);

    // 9) out = x2 + s * (kk @ w_cv)   [K = 4096]
    mma_gemm<EPI_RESID>  <<<gC, NTHR, GSMEM>>>(kk, wcvT, out, x2, s, M, CC, 4*CC);
}

// round 9
// speedup vs baseline: 2.3431x; 1.5576x over previous
#include <cuda_runtime.h>
#include <cuda_fp16.h>
#include <cstdint>
#include <cstddef>

// Problem constants
#define MB 8
#define TT 2048
#define CC 1024
#define MROWS (MB*TT)          // 16384
#define BTC (MROWS*CC)
#define BT4C (MROWS*4*CC)

// fp32 scratch
__device__ float g_h [BTC];
__device__ float g_k [BTC];
__device__ float g_v [BTC];
__device__ float g_r [BTC];
__device__ float g_x2[BTC];
__device__ float g_h2[BTC];
__device__ float g_s [BTC];
// fp16 operand scratch (single precision pass; fp16 RN == RNA-tf32 precision here)
__device__ __half g_xk[BTC];
__device__ __half g_xv[BTC];
__device__ __half g_xr[BTC];
__device__ __half g_ck[BTC];
__device__ __half g_cr[BTC];
__device__ __half g_kk[BT4C];
__device__ __half g_wkvr[3*CC*CC];   // wtkT | wtvT | wtrT  (K-major fp16)
__device__ __half g_wcks[5*CC*CC];   // wckT | wcrT
__device__ __half g_wcv [4*CC*CC];   // wcvT

// ---------------------------------------------------------------------------
// Helpers
// ---------------------------------------------------------------------------
__device__ __forceinline__ uint32_t smem_u32(const void* p){
    uint32_t a;
    asm("{ .reg .u64 t; cvta.to.shared.u64 t, %1; cvt.u32.u64 %0, t; }" : "=r"(a) : "l"(p));
    return a;
}
__device__ __forceinline__ void cp16(uint32_t dst, const void* src){
    asm volatile("cp.async.ca.shared.global [%0], [%1], 16;" :: "r"(dst), "l"(src));
}
#define CP_COMMIT() asm volatile("cp.async.commit_group;" ::: "memory")
#define CP_WAIT2()  asm volatile("cp.async.wait_group 2;" ::: "memory")
#define LDSM4(r0,r1,r2,r3,a) \
    asm volatile("ldmatrix.sync.aligned.m8n8.x4.shared.b16 {%0,%1,%2,%3}, [%4];" \
        : "=r"(r0),"=r"(r1),"=r"(r2),"=r"(r3) : "r"(a))

__device__ __forceinline__ void mma16816(float* d, const uint32_t* a, const uint32_t* b){
    asm volatile("mma.sync.aligned.m16n8k16.row.col.f32.f16.f16.f32 "
        "{%0,%1,%2,%3}, {%4,%5,%6,%7}, {%8,%9}, {%0,%1,%2,%3};"
        : "+f"(d[0]), "+f"(d[1]), "+f"(d[2]), "+f"(d[3])
        : "r"(a[0]), "r"(a[1]), "r"(a[2]), "r"(a[3]), "r"(b[0]), "r"(b[1]));
}

__device__ __forceinline__ void h4store(float4 v, __half* p){
    __half2* P = (__half2*)p;
    P[0] = __floats2half2_rn(v.x, v.y);
    P[1] = __floats2half2_rn(v.z, v.w);
}

// ---------------------------------------------------------------------------
// LayerNorm: one 256-thread block per row of C=1024 (fp32 out)
// ---------------------------------------------------------------------------
__global__ void __launch_bounds__(256) ln_kernel(
    const float* __restrict__ x, const float* __restrict__ g,
    const float* __restrict__ b, float* __restrict__ out)
{
    const int C = CC;
    size_t row = blockIdx.x;
    const float4* xr = (const float4*)(x + row * C);
    int tid = threadIdx.x;
    float4 v = xr[tid];

    float s = v.x + v.y + v.z + v.w;
    #pragma unroll
    for (int o = 16; o > 0; o >>= 1) s += __shfl_xor_sync(0xffffffffu, s, o);
    __shared__ float ws[8];
    if ((tid & 31) == 0) ws[tid >> 5] = s;
    __syncthreads();
    float mu = (ws[0]+ws[1]+ws[2]+ws[3]+ws[4]+ws[5]+ws[6]+ws[7]) * (1.0f / C);
    __syncthreads();

    float dx = v.x - mu, dy = v.y - mu, dz = v.z - mu, dw = v.w - mu;
    float s2 = dx*dx + dy*dy + dz*dz + dw*dw;
    #pragma unroll
    for (int o = 16; o > 0; o >>= 1) s2 += __shfl_xor_sync(0xffffffffu, s2, o);
    if ((tid & 31) == 0) ws[tid >> 5] = s2;
    __syncthreads();
    float var = (ws[0]+ws[1]+ws[2]+ws[3]+ws[4]+ws[5]+ws[6]+ws[7]) * (1.0f / C);
    float rstd = rsqrtf(var + 1e-5f);

    float4 gv = ((const float4*)g)[tid];
    float4 bv = ((const float4*)b)[tid];
    float4 o;
    o.x = dx * rstd * gv.x + bv.x;
    o.y = dy * rstd * gv.y + bv.y;
    o.z = dz * rstd * gv.z + bv.z;
    o.w = dw * rstd * gv.w + bv.w;
    ((float4*)(out + row * C))[tid] = o;
}

// ---------------------------------------------------------------------------
// Token-shift mixes -> fp16 operand arrays
// ---------------------------------------------------------------------------
__device__ __forceinline__ float4 mixf4(float4 h, float4 hp, float4 m){
    float4 o;
    o.x = h.x*m.x + hp.x*(1.f-m.x);
    o.y = h.y*m.y + hp.y*(1.f-m.y);
    o.z = h.z*m.z + hp.z*(1.f-m.z);
    o.w = h.w*m.w + hp.w*(1.f-m.w);
    return o;
}
__global__ void __launch_bounds__(256) mix3_kernel(
    const float* __restrict__ h, const float* __restrict__ mk,
    const float* __restrict__ mv, const float* __restrict__ mr,
    __half* xk, __half* xv, __half* xr)
{
    int j = blockIdx.x * 256 + threadIdx.x;   // float4 index
    int row = j >> 8;
    int c4  = j & 255;
    float4 hv = ((const float4*)h)[j];
    float4 hp = make_float4(0.f,0.f,0.f,0.f);
    if ((row & (TT-1)) != 0) hp = ((const float4*)h)[j - 256];
    h4store(mixf4(hv, hp, ((const float4*)mk)[c4]), xk + j*4);
    h4store(mixf4(hv, hp, ((const float4*)mv)[c4]), xv + j*4);
    h4store(mixf4(hv, hp, ((const float4*)mr)[c4]), xr + j*4);
}
__global__ void __launch_bounds__(256) mix2_kernel(
    const float* __restrict__ h, const float* __restrict__ mk,
    const float* __restrict__ mr, __half* ck, __half* cr)
{
    int j = blockIdx.x * 256 + threadIdx.x;
    int row = j >> 8;
    int c4  = j & 255;
    float4 hv = ((const float4*)h)[j];
    float4 hp = make_float4(0.f,0.f,0.f,0.f);
    if ((row & (TT-1)) != 0) hp = ((const float4*)h)[j - 256];
    h4store(mixf4(hv, hp, ((const float4*)mk)[c4]), ck + j*4);
    h4store(mixf4(hv, hp, ((const float4*)mr)[c4]), cr + j*4);
}

// ---------------------------------------------------------------------------
// WKV sequential scan, fused x + r*y epilogue. 64 thr/block, 128 blocks.
// ---------------------------------------------------------------------------
__global__ void __launch_bounds__(64) wkv_kernel(
    const float* __restrict__ kp, const float* __restrict__ vp,
    const float* __restrict__ rp, const float* __restrict__ xp,
    const float* __restrict__ wdec, const float* __restrict__ ufst,
    float* __restrict__ out)
{
    int gid = blockIdx.x * 64 + threadIdx.x;   // 0..8191
    int b = gid >> 10;
    int c = gid & (CC - 1);
    float w = wdec[c], u = ufst[c];
    float aa = 0.0f, bb = 0.0f, pp = -1e38f;
    size_t idx = ((size_t)b * TT) * CC + c;
    #pragma unroll 2
    for (int t = 0; t < TT; t++, idx += CC) {
        float kk = kp[idx];
        float vv = vp[idx];
        float rr = rp[idx];
        float xx = xp[idx];
        float uk = u + kk;
        float p  = fmaxf(pp, uk);
        float e1 = __expf(pp - p);
        float e2 = __expf(uk - p);
        float y  = (e1 * aa + e2 * vv) / (e1 + e2);
        out[idx] = xx + rr * y;
        float pw = pp + w;
        float wk = w + kk;
        float p2 = fmaxf(pw, wk);
        float e1u = __expf(pw - p2);
        float e2u = __expf(wk - p2);
        aa = e1u * aa + e2u * vv;
        bb = e1u + e2u;
        pp = p2 + __logf(bb);
    }
}

// ---------------------------------------------------------------------------
// Weight transpose + fp16 RN: src[R,Ccols] fp32 -> dst[Ccols,R] fp16
// ---------------------------------------------------------------------------
__global__ void __launch_bounds__(256) thalf_kernel(
    const float* __restrict__ src, __half* __restrict__ dst, int R, int Ccols)
{
    __shared__ float t[32][33];
    int r0 = blockIdx.y * 32, c0 = blockIdx.x * 32;
    int tx = threadIdx.x, ty = threadIdx.y;
    #pragma unroll
    for (int j = 0; j < 32; j += 8)
        t[ty + j][tx] = src[(size_t)(r0 + ty + j) * Ccols + c0 + tx];
    __syncthreads();
    #pragma unroll
    for (int j = 0; j < 32; j += 8)
        dst[(size_t)(c0 + ty + j) * R + r0 + tx] = __float2half_rn(t[tx][ty + j]);
}

// ---------------------------------------------------------------------------
// fp16 single-pass GEMM core (R4 machinery minus hi/lo split):
// C[M,N] = epi(A[M,K] @ Bt[N,K]^T), A,Bt fp16, fp32 accum.
// CTA tile 256x128, k-step 16, 4-stage cp.async pipeline, ldmatrix frags.
// Smem stage layout per operand: 8-row blocks of 16 16B chunks:
//   phys(row, c) = (row>>3)*256 + ((c<<3 | (row&7))<<4), c = k-half (0/1).
// ---------------------------------------------------------------------------
#define CTM 256
#define CTN 128
#define ST_A 8192
#define STAGE_BYTES 12288
#define GSMEM (STAGE_BYTES*4)   // 49152

#define EPI_NONE 0
#define EPI_SIGMOID 1
#define EPI_RELUSQ 2
#define EPI_RESID 3

template<int EPI>
__device__ __forceinline__ void gemm_core(
    const __half* __restrict__ A, const __half* __restrict__ Bt,
    int K, int m0, int n0B,
    float* __restrict__ outF, const float* __restrict__ resid,
    const float* __restrict__ gate,
    __half* __restrict__ outH, int Nout, int n0o)
{
    extern __shared__ char smem[];
    const uint32_t sbase = smem_u32(smem);
    const int tid = threadIdx.x;
    const int lane = tid & 31, wid = tid >> 5;
    const int wm = wid & 3, wn = wid >> 2;
    const int NS = K >> 4;

    auto load_stage = [&](int s, int buf){
        const int k0 = s << 4;
        uint32_t st = sbase + (uint32_t)buf * STAGE_BYTES;
        #pragma unroll
        for (int l = 0; l < 2; l++) {
            int chk = l*256 + tid;                  // 0..511
            int row = chk >> 1, c = chk & 1;
            uint32_t d = (uint32_t)((row>>3)<<8) | (uint32_t)((((c<<3)|(row&7)))<<4);
            cp16(st + d, A + (size_t)(m0+row)*K + k0 + c*8);
        }
        {
            int row = tid >> 1, c = tid & 1;        // 0..255 chunks
            uint32_t d = (uint32_t)((row>>3)<<8) | (uint32_t)((((c<<3)|(row&7)))<<4);
            cp16(st + ST_A + d, Bt + (size_t)(n0B+row)*K + k0 + c*8);
        }
    };

    float acc[4][8][4];
    #pragma unroll
    for (int mi = 0; mi < 4; mi++)
        #pragma unroll
        for (int ni = 0; ni < 8; ni++)
            #pragma unroll
            for (int c = 0; c < 4; c++) acc[mi][ni][c] = 0.0f;

    load_stage(0, 0); CP_COMMIT();
    load_stage(1, 1); CP_COMMIT();
    load_stage(2, 2); CP_COMMIT();

    const int rl = lane & 15, chh = lane >> 4;
    const uint32_t bpart = (uint32_t)(((rl>>3)<<8) | (((chh<<3)|(rl&7))<<4));

    for (int s = 0; s < NS; s++) {
        int buf = s & 3;
        CP_WAIT2();
        __syncthreads();
        if (s + 3 < NS) load_stage(s + 3, (s + 3) & 3);
        CP_COMMIT();

        uint32_t stA = sbase + (uint32_t)buf * STAGE_BYTES;
        uint32_t stB = stA + ST_A;

        uint32_t a[4][4], b[8][2];
        #pragma unroll
        for (int mi = 0; mi < 4; mi++) {
            uint32_t ad = stA + (uint32_t)((wm*8 + mi*2) << 8) + bpart;
            LDSM4(a[mi][0], a[mi][1], a[mi][2], a[mi][3], ad);
        }
        #pragma unroll
        for (int g = 0; g < 4; g++) {
            uint32_t bd = stB + (uint32_t)((wn*8 + g*2) << 8) + bpart;
            uint32_t r0, r1, r2, r3;
            LDSM4(r0, r1, r2, r3, bd);
            b[2*g][0] = r0;   b[2*g][1] = r2;
            b[2*g+1][0] = r1; b[2*g+1][1] = r3;
        }
        #pragma unroll
        for (int mi = 0; mi < 4; mi++)
            #pragma unroll
            for (int ni = 0; ni < 8; ni++)
                mma16816(acc[mi][ni], a[mi], b[ni]);
    }

    // ---- epilogue
    #pragma unroll
    for (int mi = 0; mi < 4; mi++) {
        int r0 = m0 + wm*64 + mi*16 + (lane >> 2);
        #pragma unroll
        for (int ni = 0; ni < 8; ni++) {
            int c0 = n0o + wn*64 + ni*8 + (lane & 3)*2;
            float v0 = acc[mi][ni][0], v1 = acc[mi][ni][1];
            float v2 = acc[mi][ni][2], v3 = acc[mi][ni][3];
            size_t i0 = (size_t)r0 * Nout + c0;
            size_t i1 = (size_t)(r0 + 8) * Nout + c0;
            if (EPI == EPI_SIGMOID) {
                v0 = 1.f/(1.f+__expf(-v0)); v1 = 1.f/(1.f+__expf(-v1));
                v2 = 1.f/(1.f+__expf(-v2)); v3 = 1.f/(1.f+__expf(-v3));
            } else if (EPI == EPI_RELUSQ) {
                v0 = fmaxf(v0,0.f); v1 = fmaxf(v1,0.f);
                v2 = fmaxf(v2,0.f); v3 = fmaxf(v3,0.f);
                *(__half2*)(outH + i0) = __floats2half2_rn(v0*v0, v1*v1);
                *(__half2*)(outH + i1) = __floats2half2_rn(v2*v2, v3*v3);
                continue;
            }
            if (EPI == EPI_RESID) {
                float2 rz0 = *(const float2*)(resid + i0);
                float2 rz1 = *(const float2*)(resid + i1);
                float2 gz0 = *(const float2*)(gate  + i0);
                float2 gz1 = *(const float2*)(gate  + i1);
                v0 = rz0.x + gz0.x*v0; v1 = rz0.y + gz0.y*v1;
                v2 = rz1.x + gz1.x*v2; v3 = rz1.y + gz1.y*v3;
            }
            *(float2*)(outF + i0) = make_float2(v0, v1);
            *(float2*)(outF + i1) = make_float2(v2, v3);
        }
    }
}

// Fused k|v|r GEMM: N-blocks 0-7 -> k, 8-15 -> v, 16-23 -> sigmoid r
__global__ void __launch_bounds__(256, 1) gemm_kvr(
    const __half* xk, const __half* xv, const __half* xr,
    const __half* Bt, float* outk, float* outv, float* outr)
{
    int seg = blockIdx.x >> 3;
    int m0  = blockIdx.y * CTM;
    int n0B = blockIdx.x * CTN;
    int n0o = (blockIdx.x & 7) * CTN;
    const __half* Aa = (seg == 0) ? xk : (seg == 1) ? xv : xr;
    float* o = (seg == 0) ? outk : (seg == 1) ? outv : outr;
    if (seg == 2)
        gemm_core<EPI_SIGMOID>(Aa, Bt, CC, m0, n0B, o, nullptr, nullptr, nullptr, CC, n0o);
    else
        gemm_core<EPI_NONE>(Aa, Bt, CC, m0, n0B, o, nullptr, nullptr, nullptr, CC, n0o);
}

// Fused kk|s GEMM: N-blocks 0-31 -> relu^2 kk (fp16), 32-39 -> sigmoid s
__global__ void __launch_bounds__(256, 1) gemm_cks(
    const __half* ck, const __half* cr, const __half* Bt,
    __half* kk, float* outs)
{
    int bx = blockIdx.x;
    int m0 = blockIdx.y * CTM;
    int n0B = bx * CTN;
    if (bx < 32)
        gemm_core<EPI_RELUSQ>(ck, Bt, CC, m0, n0B, nullptr, nullptr, nullptr, kk, 4*CC, bx*CTN);
    else
        gemm_core<EPI_SIGMOID>(cr, Bt, CC, m0, n0B, outs, nullptr, nullptr, nullptr, CC, (bx-32)*CTN);
}

// Final GEMM: out = x2 + s * (kk @ w_cv), K = 4096
__global__ void __launch_bounds__(256, 1) gemm_out(
    const __half* kk, const __half* Bt,
    float* out, const float* x2, const float* sg)
{
    int m0 = blockIdx.y * CTM;
    int n0 = blockIdx.x * CTN;
    gemm_core<EPI_RESID>(kk, Bt, 4*CC, m0, n0, out, x2, sg, nullptr, CC, n0);
}

// ---------------------------------------------------------------------------
// Host launcher
// ---------------------------------------------------------------------------
template<typename T>
static T* symaddr(const void* sym)
{
    void* p = nullptr;
    cudaGetSymbolAddress(&p, sym);
    return (T*)p;
}

extern "C" void kernel_launch(void* const* d_in, const int* in_sizes, int n_in,
                              void* d_out, int out_size)
{
    const float* x      = (const float*)d_in[0];
    const float* tdecay = (const float*)d_in[1];
    const float* tfirst = (const float*)d_in[2];
    const float* w_tk   = (const float*)d_in[3];
    const float* w_tv   = (const float*)d_in[4];
    const float* w_tr   = (const float*)d_in[5];
    const float* w_ck   = (const float*)d_in[6];
    const float* w_cv   = (const float*)d_in[7];
    const float* w_cr   = (const float*)d_in[8];
    const float* ln1_g  = (const float*)d_in[9];
    const float* ln1_b  = (const float*)d_in[10];
    const float* ln2_g  = (const float*)d_in[11];
    const float* ln2_b  = (const float*)d_in[12];
    const float* mix_k  = (const float*)d_in[13];
    const float* mix_v  = (const float*)d_in[14];
    const float* mix_r  = (const float*)d_in[15];
    const float* cmix_k = (const float*)d_in[16];
    const float* cmix_r = (const float*)d_in[17];
    float* out = (float*)d_out;

    float* h   = symaddr<float>(g_h);
    float* k   = symaddr<float>(g_k);
    float* v   = symaddr<float>(g_v);
    float* r   = symaddr<float>(g_r);
    float* x2  = symaddr<float>(g_x2);
    float* h2  = symaddr<float>(g_h2);
    float* s   = symaddr<float>(g_s);
    __half* xk = symaddr<__half>(g_xk);
    __half* xv = symaddr<__half>(g_xv);
    __half* xr = symaddr<__half>(g_xr);
    __half* ck = symaddr<__half>(g_ck);
    __half* cr = symaddr<__half>(g_cr);
    __half* kk = symaddr<__half>(g_kk);
    __half* wkvr = symaddr<__half>(g_wkvr);
    __half* wcks = symaddr<__half>(g_wcks);
    __half* wcv  = symaddr<__half>(g_wcv);

    cudaFuncSetAttribute((const void*)gemm_kvr, cudaFuncAttributeMaxDynamicSharedMemorySize, GSMEM);
    cudaFuncSetAttribute((const void*)gemm_cks, cudaFuncAttributeMaxDynamicSharedMemorySize, GSMEM);
    cudaFuncSetAttribute((const void*)gemm_out, cudaFuncAttributeMaxDynamicSharedMemorySize, GSMEM);

    const int M = MROWS;
    dim3 tb(32, 8);
    const int mixg = (BTC/4) / 256;

    // 0-2) transpose+fp16 time-mix weights into concat buffer [3072,1024]
    thalf_kernel<<<dim3(CC/32, CC/32), tb>>>(w_tk, wkvr,           CC, CC);
    thalf_kernel<<<dim3(CC/32, CC/32), tb>>>(w_tv, wkvr + CC*CC,   CC, CC);
    thalf_kernel<<<dim3(CC/32, CC/32), tb>>>(w_tr, wkvr + 2*CC*CC, CC, CC);

    // 3) h = LN1(x);  4) token-shift mixes (fp16)
    ln_kernel<<<M, 256>>>(x, ln1_g, ln1_b, h);
    mix3_kernel<<<mixg, 256>>>(h, mix_k, mix_v, mix_r, xk, xv, xr);

    // 5) fused k|v|r GEMM
    gemm_kvr<<<dim3(24, M/CTM), 256, GSMEM>>>(xk, xv, xr, wkvr, k, v, r);

    // 6) x2 = x + r * WKV(k, v)
    wkv_kernel<<<128, 64>>>(k, v, r, x, tdecay, tfirst, x2);

    // 7) h2 = LN2(x2);  8) channel mixes
    ln_kernel<<<M, 256>>>(x2, ln2_g, ln2_b, h2);
    mix2_kernel<<<mixg, 256>>>(h2, cmix_k, cmix_r, ck, cr);

    // 9-11) transpose+fp16 channel weights: concat [5120,1024] and [1024,4096]
    thalf_kernel<<<dim3(4*CC/32, CC/32), tb>>>(w_ck, wcks,           CC, 4*CC);
    thalf_kernel<<<dim3(CC/32, CC/32),   tb>>>(w_cr, wcks + 4*CC*CC, CC, CC);
    thalf_kernel<<<dim3(CC/32, 4*CC/32), tb>>>(w_cv, wcv,            4*CC, CC);

    // 12) fused kk|s GEMM: kk = relu(ck@w_ck)^2 (fp16), s = sigmoid(cr@w_cr)
    gemm_cks<<<dim3(40, M/CTM), 256, GSMEM>>>(ck, cr, wcks, kk, s);

    // 13) out = x2 + s * (kk @ w_cv), K = 4096
    gemm_out<<<dim3(8, M/CTM), 256, GSMEM>>>(kk, wcv, out, x2, s);
}

// round 11
// speedup vs baseline: 2.3947x; 1.0220x over previous
#include <cuda_runtime.h>
#include <cuda_fp16.h>
#include <cstdint>
#include <cstddef>

// Problem constants
#define MB 8
#define TT 2048
#define CC 1024
#define MROWS (MB*TT)          // 16384
#define BTC (MROWS*CC)
#define BT4C (MROWS*4*CC)
#define NCH 16
#define CHL (TT/NCH)           // 128

// fp32 scratch
__device__ float g_h [BTC];
__device__ float g_k [BTC];
__device__ float g_v [BTC];
__device__ float g_r [BTC];
__device__ float g_x2[BTC];
__device__ float g_h2[BTC];
__device__ float g_s [BTC];
// WKV chunk aggregates: layout [b][chunk][c]
__device__ float g_ppl[MB*NCH*CC];
__device__ float g_alp[MB*NCH*CC];
__device__ float g_bet[MB*NCH*CC];
// fp16 operand scratch
__device__ __half g_xk[BTC];
__device__ __half g_xv[BTC];
__device__ __half g_xr[BTC];
__device__ __half g_ck[BTC];
__device__ __half g_cr[BTC];
__device__ __half g_kk[BT4C];
__device__ __half g_wkvr[3*CC*CC];   // wtkT | wtvT | wtrT  (K-major fp16)
__device__ __half g_wcks[5*CC*CC];   // wckT | wcrT
__device__ __half g_wcv [4*CC*CC];   // wcvT

// ---------------------------------------------------------------------------
// Helpers
// ---------------------------------------------------------------------------
__device__ __forceinline__ uint32_t smem_u32(const void* p){
    uint32_t a;
    asm("{ .reg .u64 t; cvta.to.shared.u64 t, %1; cvt.u32.u64 %0, t; }" : "=r"(a) : "l"(p));
    return a;
}
__device__ __forceinline__ void cp16(uint32_t dst, const void* src){
    asm volatile("cp.async.ca.shared.global [%0], [%1], 16;" :: "r"(dst), "l"(src));
}
#define CP_COMMIT() asm volatile("cp.async.commit_group;" ::: "memory")
#define CP_WAIT2()  asm volatile("cp.async.wait_group 2;" ::: "memory")
#define LDSM4(r0,r1,r2,r3,a) \
    asm volatile("ldmatrix.sync.aligned.m8n8.x4.shared.b16 {%0,%1,%2,%3}, [%4];" \
        : "=r"(r0),"=r"(r1),"=r"(r2),"=r"(r3) : "r"(a))

__device__ __forceinline__ void mma16816(float* d, const uint32_t* a, const uint32_t* b){
    asm volatile("mma.sync.aligned.m16n8k16.row.col.f32.f16.f16.f32 "
        "{%0,%1,%2,%3}, {%4,%5,%6,%7}, {%8,%9}, {%0,%1,%2,%3};"
        : "+f"(d[0]), "+f"(d[1]), "+f"(d[2]), "+f"(d[3])
        : "r"(a[0]), "r"(a[1]), "r"(a[2]), "r"(a[3]), "r"(b[0]), "r"(b[1]));
}

__device__ __forceinline__ void h4store(float4 v, __half* p){
    __half2* P = (__half2*)p;
    P[0] = __floats2half2_rn(v.x, v.y);
    P[1] = __floats2half2_rn(v.z, v.w);
}

// ---------------------------------------------------------------------------
// LayerNorm: one 256-thread block per row of C=1024 (fp32 out)
// ---------------------------------------------------------------------------
__global__ void __launch_bounds__(256) ln_kernel(
    const float* __restrict__ x, const float* __restrict__ g,
    const float* __restrict__ b, float* __restrict__ out)
{
    const int C = CC;
    size_t row = blockIdx.x;
    const float4* xr = (const float4*)(x + row * C);
    int tid = threadIdx.x;
    float4 v = xr[tid];

    float s = v.x + v.y + v.z + v.w;
    #pragma unroll
    for (int o = 16; o > 0; o >>= 1) s += __shfl_xor_sync(0xffffffffu, s, o);
    __shared__ float ws[8];
    if ((tid & 31) == 0) ws[tid >> 5] = s;
    __syncthreads();
    float mu = (ws[0]+ws[1]+ws[2]+ws[3]+ws[4]+ws[5]+ws[6]+ws[7]) * (1.0f / C);
    __syncthreads();

    float dx = v.x - mu, dy = v.y - mu, dz = v.z - mu, dw = v.w - mu;
    float s2 = dx*dx + dy*dy + dz*dz + dw*dw;
    #pragma unroll
    for (int o = 16; o > 0; o >>= 1) s2 += __shfl_xor_sync(0xffffffffu, s2, o);
    if ((tid & 31) == 0) ws[tid >> 5] = s2;
    __syncthreads();
    float var = (ws[0]+ws[1]+ws[2]+ws[3]+ws[4]+ws[5]+ws[6]+ws[7]) * (1.0f / C);
    float rstd = rsqrtf(var + 1e-5f);

    float4 gv = ((const float4*)g)[tid];
    float4 bv = ((const float4*)b)[tid];
    float4 o;
    o.x = dx * rstd * gv.x + bv.x;
    o.y = dy * rstd * gv.y + bv.y;
    o.z = dz * rstd * gv.z + bv.z;
    o.w = dw * rstd * gv.w + bv.w;
    ((float4*)(out + row * C))[tid] = o;
}

// ---------------------------------------------------------------------------
// Token-shift mixes -> fp16 operand arrays
// ---------------------------------------------------------------------------
__device__ __forceinline__ float4 mixf4(float4 h, float4 hp, float4 m){
    float4 o;
    o.x = h.x*m.x + hp.x*(1.f-m.x);
    o.y = h.y*m.y + hp.y*(1.f-m.y);
    o.z = h.z*m.z + hp.z*(1.f-m.z);
    o.w = h.w*m.w + hp.w*(1.f-m.w);
    return o;
}
__global__ void __launch_bounds__(256) mix3_kernel(
    const float* __restrict__ h, const float* __restrict__ mk,
    const float* __restrict__ mv, const float* __restrict__ mr,
    __half* xk, __half* xv, __half* xr)
{
    int j = blockIdx.x * 256 + threadIdx.x;   // float4 index
    int row = j >> 8;
    int c4  = j & 255;
    float4 hv = ((const float4*)h)[j];
    float4 hp = make_float4(0.f,0.f,0.f,0.f);
    if ((row & (TT-1)) != 0) hp = ((const float4*)h)[j - 256];
    h4store(mixf4(hv, hp, ((const float4*)mk)[c4]), xk + j*4);
    h4store(mixf4(hv, hp, ((const float4*)mv)[c4]), xv + j*4);
    h4store(mixf4(hv, hp, ((const float4*)mr)[c4]), xr + j*4);
}
__global__ void __launch_bounds__(256) mix2_kernel(
    const float* __restrict__ h, const float* __restrict__ mk,
    const float* __restrict__ mr, __half* ck, __half* cr)
{
    int j = blockIdx.x * 256 + threadIdx.x;
    int row = j >> 8;
    int c4  = j & 255;
    float4 hv = ((const float4*)h)[j];
    float4 hp = make_float4(0.f,0.f,0.f,0.f);
    if ((row & (TT-1)) != 0) hp = ((const float4*)h)[j - 256];
    h4store(mixf4(hv, hp, ((const float4*)mk)[c4]), ck + j*4);
    h4store(mixf4(hv, hp, ((const float4*)mr)[c4]), cr + j*4);
}

// ---------------------------------------------------------------------------
// WKV chunked 3-pass scan. Thread map: gid -> c (fast, 1024), chunk, b.
//   State (aa, pp); pp_t = log P_t with P' = e^w(P + e^k)  -> LSE-associative.
//   Given the pp path, aa' = e1u*aa + e2u*v is affine in aa_in:
//     alpha = prod(e1u) in (0,1], beta = aa with zero init.
// pass1: per-chunk pp_loc (scan k).
// pass2: fold pp_in from pp_locs, replay pp path, emit (alpha, beta).
// pass3: fold pp_in and aa_in, replay chunk exactly as reference, write out.
// ---------------------------------------------------------------------------
__global__ void __launch_bounds__(256) wkv_p1(
    const float* __restrict__ kp, const float* __restrict__ wdec,
    float* __restrict__ ppl)
{
    int gid = blockIdx.x * 256 + threadIdx.x;   // 0..131071
    int c  = gid & (CC - 1);
    int ch = (gid >> 10) & (NCH - 1);
    int b  = gid >> 14;
    float w = wdec[c];
    float pp = -1e38f;
    size_t idx = ((size_t)b * TT + (size_t)ch * CHL) * CC + c;
    #pragma unroll 2
    for (int t = 0; t < CHL; t++, idx += CC) {
        float kk = kp[idx];
        float pw = pp + w, wk = w + kk;
        float p2 = fmaxf(pw, wk);
        pp = p2 + __logf(__expf(pw - p2) + __expf(wk - p2));
    }
    ppl[((size_t)b * NCH + ch) * CC + c] = pp;
}

__device__ __forceinline__ float fold_pp(
    const float* __restrict__ ppl, int b, int c, int ch, float Lw)
{
    float pin = -1e38f;
    for (int j = 0; j < ch; j++) {
        float a  = pin + Lw;
        float pl = ppl[((size_t)b * NCH + j) * CC + c];
        float m  = fmaxf(a, pl);
        pin = m + __logf(__expf(a - m) + __expf(pl - m));
    }
    return pin;
}

__global__ void __launch_bounds__(256) wkv_p2(
    const float* __restrict__ kp, const float* __restrict__ vp,
    const float* __restrict__ wdec, const float* __restrict__ ppl,
    float* __restrict__ alp, float* __restrict__ bet)
{
    int gid = blockIdx.x * 256 + threadIdx.x;
    int c  = gid & (CC - 1);
    int ch = (gid >> 10) & (NCH - 1);
    int b  = gid >> 14;
    float w = wdec[c];
    float pp = fold_pp(ppl, b, c, ch, (float)CHL * w);
    float alpha = 1.0f, beta = 0.0f;
    size_t idx = ((size_t)b * TT + (size_t)ch * CHL) * CC + c;
    #pragma unroll 2
    for (int t = 0; t < CHL; t++, idx += CC) {
        float kk = kp[idx], vv = vp[idx];
        float pw = pp + w, wk = w + kk;
        float p2 = fmaxf(pw, wk);
        float e1u = __expf(pw - p2);
        float e2u = __expf(wk - p2);
        alpha *= e1u;
        beta = e1u * beta + e2u * vv;
        pp = p2 + __logf(e1u + e2u);
    }
    size_t o = ((size_t)b * NCH + ch) * CC + c;
    alp[o] = alpha;
    bet[o] = beta;
}

__global__ void __launch_bounds__(256) wkv_p3(
    const float* __restrict__ kp, const float* __restrict__ vp,
    const float* __restrict__ rp, const float* __restrict__ xp,
    const float* __restrict__ wdec, const float* __restrict__ ufst,
    const float* __restrict__ ppl, const float* __restrict__ alp,
    const float* __restrict__ bet, float* __restrict__ out)
{
    int gid = blockIdx.x * 256 + threadIdx.x;
    int c  = gid & (CC - 1);
    int ch = (gid >> 10) & (NCH - 1);
    int b  = gid >> 14;
    float w = wdec[c], u = ufst[c];
    float pp = fold_pp(ppl, b, c, ch, (float)CHL * w);
    float aa = 0.0f;
    for (int j = 0; j < ch; j++) {
        size_t o = ((size_t)b * NCH + j) * CC + c;
        aa = alp[o] * aa + bet[o];
    }
    size_t idx = ((size_t)b * TT + (size_t)ch * CHL) * CC + c;
    #pragma unroll 2
    for (int t = 0; t < CHL; t++, idx += CC) {
        float kk = kp[idx];
        float vv = vp[idx];
        float rr = rp[idx];
        float xx = xp[idx];
        float uk = u + kk;
        float p  = fmaxf(pp, uk);
        float e1 = __expf(pp - p);
        float e2 = __expf(uk - p);
        float y  = (e1 * aa + e2 * vv) / (e1 + e2);
        out[idx] = xx + rr * y;
        float pw = pp + w;
        float wk = w + kk;
        float p2 = fmaxf(pw, wk);
        float e1u = __expf(pw - p2);
        float e2u = __expf(wk - p2);
        aa = e1u * aa + e2u * vv;
        pp = p2 + __logf(e1u + e2u);
    }
}

// ---------------------------------------------------------------------------
// Weight transpose + fp16 RN: src[R,Ccols] fp32 -> dst[Ccols,R] fp16
// ---------------------------------------------------------------------------
__global__ void __launch_bounds__(256) thalf_kernel(
    const float* __restrict__ src, __half* __restrict__ dst, int R, int Ccols)
{
    __shared__ float t[32][33];
    int r0 = blockIdx.y * 32, c0 = blockIdx.x * 32;
    int tx = threadIdx.x, ty = threadIdx.y;
    #pragma unroll
    for (int j = 0; j < 32; j += 8)
        t[ty + j][tx] = src[(size_t)(r0 + ty + j) * Ccols + c0 + tx];
    __syncthreads();
    #pragma unroll
    for (int j = 0; j < 32; j += 8)
        dst[(size_t)(c0 + ty + j) * R + r0 + tx] = __float2half_rn(t[tx][ty + j]);
}

// ---------------------------------------------------------------------------
// fp16 single-pass GEMM core: C[M,N] = epi(A[M,K] @ Bt[N,K]^T), fp32 accum.
// CTA tile 256x128, k-step 16, 4-stage cp.async pipeline, ldmatrix frags.
// phys(row, c) = (row>>3)*256 + ((c<<3 | (row&7))<<4), c = k-half (0/1).
// ---------------------------------------------------------------------------
#define CTM 256
#define CTN 128
#define ST_A 8192
#define STAGE_BYTES 12288
#define GSMEM (STAGE_BYTES*4)   // 49152

#define EPI_NONE 0
#define EPI_SIGMOID 1
#define EPI_RELUSQ 2
#define EPI_RESID 3

template<int EPI>
__device__ __forceinline__ void gemm_core(
    const __half* __restrict__ A, const __half* __restrict__ Bt,
    int K, int m0, int n0B,
    float* __restrict__ outF, const float* __restrict__ resid,
    const float* __restrict__ gate,
    __half* __restrict__ outH, int Nout, int n0o)
{
    extern __shared__ char smem[];
    const uint32_t sbase = smem_u32(smem);
    const int tid = threadIdx.x;
    const int lane = tid & 31, wid = tid >> 5;
    const int wm = wid & 3, wn = wid >> 2;
    const int NS = K >> 4;

    auto load_stage = [&](int s, int buf){
        const int k0 = s << 4;
        uint32_t st = sbase + (uint32_t)buf * STAGE_BYTES;
        #pragma unroll
        for (int l = 0; l < 2; l++) {
            int chk = l*256 + tid;                  // 0..511
            int row = chk >> 1, c = chk & 1;
            uint32_t d = (uint32_t)((row>>3)<<8) | (uint32_t)((((c<<3)|(row&7)))<<4);
            cp16(st + d, A + (size_t)(m0+row)*K + k0 + c*8);
        }
        {
            int row = tid >> 1, c = tid & 1;        // 0..255 chunks
            uint32_t d = (uint32_t)((row>>3)<<8) | (uint32_t)((((c<<3)|(row&7)))<<4);
            cp16(st + ST_A + d, Bt + (size_t)(n0B+row)*K + k0 + c*8);
        }
    };

    float acc[4][8][4];
    #pragma unroll
    for (int mi = 0; mi < 4; mi++)
        #pragma unroll
        for (int ni = 0; ni < 8; ni++)
            #pragma unroll
            for (int c = 0; c < 4; c++) acc[mi][ni][c] = 0.0f;

    load_stage(0, 0); CP_COMMIT();
    load_stage(1, 1); CP_COMMIT();
    load_stage(2, 2); CP_COMMIT();

    const int rl = lane & 15, chh = lane >> 4;
    const uint32_t bpart = (uint32_t)(((rl>>3)<<8) | (((chh<<3)|(rl&7))<<4));

    for (int s = 0; s < NS; s++) {
        int buf = s & 3;
        CP_WAIT2();
        __syncthreads();
        if (s + 3 < NS) load_stage(s + 3, (s + 3) & 3);
        CP_COMMIT();

        uint32_t stA = sbase + (uint32_t)buf * STAGE_BYTES;
        uint32_t stB = stA + ST_A;

        uint32_t a[4][4], b[8][2];
        #pragma unroll
        for (int mi = 0; mi < 4; mi++) {
            uint32_t ad = stA + (uint32_t)((wm*8 + mi*2) << 8) + bpart;
            LDSM4(a[mi][0], a[mi][1], a[mi][2], a[mi][3], ad);
        }
        #pragma unroll
        for (int g = 0; g < 4; g++) {
            uint32_t bd = stB + (uint32_t)((wn*8 + g*2) << 8) + bpart;
            uint32_t r0, r1, r2, r3;
            LDSM4(r0, r1, r2, r3, bd);
            b[2*g][0] = r0;   b[2*g][1] = r2;
            b[2*g+1][0] = r1; b[2*g+1][1] = r3;
        }
        #pragma unroll
        for (int mi = 0; mi < 4; mi++)
            #pragma unroll
            for (int ni = 0; ni < 8; ni++)
                mma16816(acc[mi][ni], a[mi], b[ni]);
    }

    // ---- epilogue
    #pragma unroll
    for (int mi = 0; mi < 4; mi++) {
        int r0 = m0 + wm*64 + mi*16 + (lane >> 2);
        #pragma unroll
        for (int ni = 0; ni < 8; ni++) {
            int c0 = n0o + wn*64 + ni*8 + (lane & 3)*2;
            float v0 = acc[mi][ni][0], v1 = acc[mi][ni][1];
            float v2 = acc[mi][ni][2], v3 = acc[mi][ni][3];
            size_t i0 = (size_t)r0 * Nout + c0;
            size_t i1 = (size_t)(r0 + 8) * Nout + c0;
            if (EPI == EPI_SIGMOID) {
                v0 = 1.f/(1.f+__expf(-v0)); v1 = 1.f/(1.f+__expf(-v1));
                v2 = 1.f/(1.f+__expf(-v2)); v3 = 1.f/(1.f+__expf(-v3));
            } else if (EPI == EPI_RELUSQ) {
                v0 = fmaxf(v0,0.f); v1 = fmaxf(v1,0.f);
                v2 = fmaxf(v2,0.f); v3 = fmaxf(v3,0.f);
                *(__half2*)(outH + i0) = __floats2half2_rn(v0*v0, v1*v1);
                *(__half2*)(outH + i1) = __floats2half2_rn(v2*v2, v3*v3);
                continue;
            }
            if (EPI == EPI_RESID) {
                float2 rz0 = *(const float2*)(resid + i0);
                float2 rz1 = *(const float2*)(resid + i1);
                float2 gz0 = *(const float2*)(gate  + i0);
                float2 gz1 = *(const float2*)(gate  + i1);
                v0 = rz0.x + gz0.x*v0; v1 = rz0.y + gz0.y*v1;
                v2 = rz1.x + gz1.x*v2; v3 = rz1.y + gz1.y*v3;
            }
            *(float2*)(outF + i0) = make_float2(v0, v1);
            *(float2*)(outF + i1) = make_float2(v2, v3);
        }
    }
}

// Fused k|v|r GEMM: N-blocks 0-7 -> k, 8-15 -> v, 16-23 -> sigmoid r
__global__ void __launch_bounds__(256, 1) gemm_kvr(
    const __half* xk, const __half* xv, const __half* xr,
    const __half* Bt, float* outk, float* outv, float* outr)
{
    int seg = blockIdx.x >> 3;
    int m0  = blockIdx.y * CTM;
    int n0B = blockIdx.x * CTN;
    int n0o = (blockIdx.x & 7) * CTN;
    const __half* Aa = (seg == 0) ? xk : (seg == 1) ? xv : xr;
    float* o = (seg == 0) ? outk : (seg == 1) ? outv : outr;
    if (seg == 2)
        gemm_core<EPI_SIGMOID>(Aa, Bt, CC, m0, n0B, o, nullptr, nullptr, nullptr, CC, n0o);
    else
        gemm_core<EPI_NONE>(Aa, Bt, CC, m0, n0B, o, nullptr, nullptr, nullptr, CC, n0o);
}

// Fused kk|s GEMM: N-blocks 0-31 -> relu^2 kk (fp16), 32-39 -> sigmoid s
__global__ void __launch_bounds__(256, 1) gemm_cks(
    const __half* ck, const __half* cr, const __half* Bt,
    __half* kk, float* outs)
{
    int bx = blockIdx.x;
    int m0 = blockIdx.y * CTM;
    int n0B = bx * CTN;
    if (bx < 32)
        gemm_core<EPI_RELUSQ>(ck, Bt, CC, m0, n0B, nullptr, nullptr, nullptr, kk, 4*CC, bx*CTN);
    else
        gemm_core<EPI_SIGMOID>(cr, Bt, CC, m0, n0B, outs, nullptr, nullptr, nullptr, CC, (bx-32)*CTN);
}

// Final GEMM: out = x2 + s * (kk @ w_cv), K = 4096
__global__ void __launch_bounds__(256, 1) gemm_out(
    const __half* kk, const __half* Bt,
    float* out, const float* x2, const float* sg)
{
    int m0 = blockIdx.y * CTM;
    int n0 = blockIdx.x * CTN;
    gemm_core<EPI_RESID>(kk, Bt, 4*CC, m0, n0, out, x2, sg, nullptr, CC, n0);
}

// ---------------------------------------------------------------------------
// Host launcher
// ---------------------------------------------------------------------------
template<typename T>
static T* symaddr(const void* sym)
{
    void* p = nullptr;
    cudaGetSymbolAddress(&p, sym);
    return (T*)p;
}

extern "C" void kernel_launch(void* const* d_in, const int* in_sizes, int n_in,
                              void* d_out, int out_size)
{
    const float* x      = (const float*)d_in[0];
    const float* tdecay = (const float*)d_in[1];
    const float* tfirst = (const float*)d_in[2];
    const float* w_tk   = (const float*)d_in[3];
    const float* w_tv   = (const float*)d_in[4];
    const float* w_tr   = (const float*)d_in[5];
    const float* w_ck   = (const float*)d_in[6];
    const float* w_cv   = (const float*)d_in[7];
    const float* w_cr   = (const float*)d_in[8];
    const float* ln1_g  = (const float*)d_in[9];
    const float* ln1_b  = (const float*)d_in[10];
    const float* ln2_g  = (const float*)d_in[11];
    const float* ln2_b  = (const float*)d_in[12];
    const float* mix_k  = (const float*)d_in[13];
    const float* mix_v  = (const float*)d_in[14];
    const float* mix_r  = (const float*)d_in[15];
    const float* cmix_k = (const float*)d_in[16];
    const float* cmix_r = (const float*)d_in[17];
    float* out = (float*)d_out;

    float* h   = symaddr<float>(g_h);
    float* k   = symaddr<float>(g_k);
    float* v   = symaddr<float>(g_v);
    float* r   = symaddr<float>(g_r);
    float* x2  = symaddr<float>(g_x2);
    float* h2  = symaddr<float>(g_h2);
    float* s   = symaddr<float>(g_s);
    float* ppl = symaddr<float>(g_ppl);
    float* alp = symaddr<float>(g_alp);
    float* bet = symaddr<float>(g_bet);
    __half* xk = symaddr<__half>(g_xk);
    __half* xv = symaddr<__half>(g_xv);
    __half* xr = symaddr<__half>(g_xr);
    __half* ck = symaddr<__half>(g_ck);
    __half* cr = symaddr<__half>(g_cr);
    __half* kk = symaddr<__half>(g_kk);
    __half* wkvr = symaddr<__half>(g_wkvr);
    __half* wcks = symaddr<__half>(g_wcks);
    __half* wcv  = symaddr<__half>(g_wcv);

    cudaFuncSetAttribute((const void*)gemm_kvr, cudaFuncAttributeMaxDynamicSharedMemorySize, GSMEM);
    cudaFuncSetAttribute((const void*)gemm_cks, cudaFuncAttributeMaxDynamicSharedMemorySize, GSMEM);
    cudaFuncSetAttribute((const void*)gemm_out, cudaFuncAttributeMaxDynamicSharedMemorySize, GSMEM);

    const int M = MROWS;
    dim3 tb(32, 8);
    const int mixg = (BTC/4) / 256;
    const int wkvg = (MB * CC * NCH) / 256;   // 512 blocks

    // 0-2) transpose+fp16 time-mix weights into concat buffer [3072,1024]
    thalf_kernel<<<dim3(CC/32, CC/32), tb>>>(w_tk, wkvr,           CC, CC);
    thalf_kernel<<<dim3(CC/32, CC/32), tb>>>(w_tv, wkvr + CC*CC,   CC, CC);
    thalf_kernel<<<dim3(CC/32, CC/32), tb>>>(w_tr, wkvr + 2*CC*CC, CC, CC);

    // 3) h = LN1(x);  4) token-shift mixes (fp16)
    ln_kernel<<<M, 256>>>(x, ln1_g, ln1_b, h);
    mix3_kernel<<<mixg, 256>>>(h, mix_k, mix_v, mix_r, xk, xv, xr);

    // 5) fused k|v|r GEMM
    gemm_kvr<<<dim3(24, M/CTM), 256, GSMEM>>>(xk, xv, xr, wkvr, k, v, r);

    // 6) x2 = x + r * WKV(k, v)  — chunked 3-pass scan
    wkv_p1<<<wkvg, 256>>>(k, tdecay, ppl);
    wkv_p2<<<wkvg, 256>>>(k, v, tdecay, ppl, alp, bet);
    wkv_p3<<<wkvg, 256>>>(k, v, r, x, tdecay, tfirst, ppl, alp, bet, x2);

    // 7) h2 = LN2(x2);  8) channel mixes
    ln_kernel<<<M, 256>>>(x2, ln2_g, ln2_b, h2);
    mix2_kernel<<<mixg, 256>>>(h2, cmix_k, cmix_r, ck, cr);

    // 9-11) transpose+fp16 channel weights: concat [5120,1024] and [1024,4096]
    thalf_kernel<<<dim3(4*CC/32, CC/32), tb>>>(w_ck, wcks,           CC, 4*CC);
    thalf_kernel<<<dim3(CC/32, CC/32),   tb>>>(w_cr, wcks + 4*CC*CC, CC, CC);
    thalf_kernel<<<dim3(CC/32, 4*CC/32), tb>>>(w_cv, wcv,            4*CC, CC);

    // 12) fused kk|s GEMM: kk = relu(ck@w_ck)^2 (fp16), s = sigmoid(cr@w_cr)
    gemm_cks<<<dim3(40, M/CTM), 256, GSMEM>>>(ck, cr, wcks, kk, s);

    // 13) out = x2 + s * (kk @ w_cv), K = 4096
    gemm_out<<<dim3(8, M/CTM), 256, GSMEM>>>(kk, wcv, out, x2, s);
}

// round 12
// speedup vs baseline: 3.6559x; 1.5267x over previous
#include <cuda_runtime.h>
#include <cuda_fp16.h>
#include <cstdint>
#include <cstddef>

// Problem constants
#define MB 8
#define TT 2048
#define CC 1024
#define MROWS (MB*TT)          // 16384
#define BTC (MROWS*CC)
#define BT4C (MROWS*4*CC)
#define NCH 16
#define CHL (TT/NCH)           // 128

// fp32 scratch
__device__ float g_h [BTC];
__device__ float g_k [BTC];
__device__ float g_v [BTC];
__device__ float g_r [BTC];
__device__ float g_x2[BTC];
__device__ float g_h2[BTC];
__device__ float g_s [BTC];
// WKV chunk aggregates: layout [b][chunk][c]
__device__ float g_ppl[MB*NCH*CC];
__device__ float g_alp[MB*NCH*CC];
__device__ float g_bet[MB*NCH*CC];
// fp16 operand scratch
__device__ __half g_xk[BTC];
__device__ __half g_xv[BTC];
__device__ __half g_xr[BTC];
__device__ __half g_ck[BTC];
__device__ __half g_cr[BTC];
__device__ __half g_kk[BT4C];
__device__ __half g_wkvr[3*CC*CC];   // wtkT | wtvT | wtrT  (K-major fp16)
__device__ __half g_wcks[5*CC*CC];   // wckT | wcrT
__device__ __half g_wcv [4*CC*CC];   // wcvT

// ---------------------------------------------------------------------------
// Helpers
// ---------------------------------------------------------------------------
__device__ __forceinline__ uint32_t smem_u32(const void* p){
    uint32_t a;
    asm("{ .reg .u64 t; cvta.to.shared.u64 t, %1; cvt.u32.u64 %0, t; }" : "=r"(a) : "l"(p));
    return a;
}
__device__ __forceinline__ void cp16(uint32_t dst, const void* src){
    asm volatile("cp.async.ca.shared.global [%0], [%1], 16;" :: "r"(dst), "l"(src));
}
#define CP_COMMIT() asm volatile("cp.async.commit_group;" ::: "memory")
#define CP_WAIT2()  asm volatile("cp.async.wait_group 2;" ::: "memory")
#define LDSM4(r0,r1,r2,r3,a) \
    asm volatile("ldmatrix.sync.aligned.m8n8.x4.shared.b16 {%0,%1,%2,%3}, [%4];" \
        : "=r"(r0),"=r"(r1),"=r"(r2),"=r"(r3) : "r"(a))

__device__ __forceinline__ void mma16816(float* d, const uint32_t* a, const uint32_t* b){
    asm volatile("mma.sync.aligned.m16n8k16.row.col.f32.f16.f16.f32 "
        "{%0,%1,%2,%3}, {%4,%5,%6,%7}, {%8,%9}, {%0,%1,%2,%3};"
        : "+f"(d[0]), "+f"(d[1]), "+f"(d[2]), "+f"(d[3])
        : "r"(a[0]), "r"(a[1]), "r"(a[2]), "r"(a[3]), "r"(b[0]), "r"(b[1]));
}

__device__ __forceinline__ void h4store(float4 v, __half* p){
    __half2* P = (__half2*)p;
    P[0] = __floats2half2_rn(v.x, v.y);
    P[1] = __floats2half2_rn(v.z, v.w);
}

// ---------------------------------------------------------------------------
// LayerNorm: one 256-thread block per row of C=1024 (fp32 out)
// ---------------------------------------------------------------------------
__global__ void __launch_bounds__(256) ln_kernel(
    const float* __restrict__ x, const float* __restrict__ g,
    const float* __restrict__ b, float* __restrict__ out)
{
    const int C = CC;
    size_t row = blockIdx.x;
    const float4* xr = (const float4*)(x + row * C);
    int tid = threadIdx.x;
    float4 v = xr[tid];

    float s = v.x + v.y + v.z + v.w;
    #pragma unroll
    for (int o = 16; o > 0; o >>= 1) s += __shfl_xor_sync(0xffffffffu, s, o);
    __shared__ float ws[8];
    if ((tid & 31) == 0) ws[tid >> 5] = s;
    __syncthreads();
    float mu = (ws[0]+ws[1]+ws[2]+ws[3]+ws[4]+ws[5]+ws[6]+ws[7]) * (1.0f / C);
    __syncthreads();

    float dx = v.x - mu, dy = v.y - mu, dz = v.z - mu, dw = v.w - mu;
    float s2 = dx*dx + dy*dy + dz*dz + dw*dw;
    #pragma unroll
    for (int o = 16; o > 0; o >>= 1) s2 += __shfl_xor_sync(0xffffffffu, s2, o);
    if ((tid & 31) == 0) ws[tid >> 5] = s2;
    __syncthreads();
    float var = (ws[0]+ws[1]+ws[2]+ws[3]+ws[4]+ws[5]+ws[6]+ws[7]) * (1.0f / C);
    float rstd = rsqrtf(var + 1e-5f);

    float4 gv = ((const float4*)g)[tid];
    float4 bv = ((const float4*)b)[tid];
    float4 o;
    o.x = dx * rstd * gv.x + bv.x;
    o.y = dy * rstd * gv.y + bv.y;
    o.z = dz * rstd * gv.z + bv.z;
    o.w = dw * rstd * gv.w + bv.w;
    ((float4*)(out + row * C))[tid] = o;
}

// ---------------------------------------------------------------------------
// Token-shift mixes -> fp16 operand arrays
// ---------------------------------------------------------------------------
__device__ __forceinline__ float4 mixf4(float4 h, float4 hp, float4 m){
    float4 o;
    o.x = h.x*m.x + hp.x*(1.f-m.x);
    o.y = h.y*m.y + hp.y*(1.f-m.y);
    o.z = h.z*m.z + hp.z*(1.f-m.z);
    o.w = h.w*m.w + hp.w*(1.f-m.w);
    return o;
}
__global__ void __launch_bounds__(256) mix3_kernel(
    const float* __restrict__ h, const float* __restrict__ mk,
    const float* __restrict__ mv, const float* __restrict__ mr,
    __half* xk, __half* xv, __half* xr)
{
    int j = blockIdx.x * 256 + threadIdx.x;   // float4 index
    int row = j >> 8;
    int c4  = j & 255;
    float4 hv = ((const float4*)h)[j];
    float4 hp = make_float4(0.f,0.f,0.f,0.f);
    if ((row & (TT-1)) != 0) hp = ((const float4*)h)[j - 256];
    h4store(mixf4(hv, hp, ((const float4*)mk)[c4]), xk + j*4);
    h4store(mixf4(hv, hp, ((const float4*)mv)[c4]), xv + j*4);
    h4store(mixf4(hv, hp, ((const float4*)mr)[c4]), xr + j*4);
}
__global__ void __launch_bounds__(256) mix2_kernel(
    const float* __restrict__ h, const float* __restrict__ mk,
    const float* __restrict__ mr, __half* ck, __half* cr)
{
    int j = blockIdx.x * 256 + threadIdx.x;
    int row = j >> 8;
    int c4  = j & 255;
    float4 hv = ((const float4*)h)[j];
    float4 hp = make_float4(0.f,0.f,0.f,0.f);
    if ((row & (TT-1)) != 0) hp = ((const float4*)h)[j - 256];
    h4store(mixf4(hv, hp, ((const float4*)mk)[c4]), ck + j*4);
    h4store(mixf4(hv, hp, ((const float4*)mr)[c4]), cr + j*4);
}

// ---------------------------------------------------------------------------
// WKV chunked 3-pass scan. Thread map: gid -> c (fast, 1024), chunk, b.
//   State (aa, pp); pp_t = log P_t with P' = e^w(P + e^k)  -> LSE-associative.
//   Given the pp path, aa' = e1u*aa + e2u*v is affine in aa_in:
//     alpha = prod(e1u) in (0,1], beta = aa with zero init.
// pass1: per-chunk pp_loc (scan k).
// pass2: fold pp_in from pp_locs, replay pp path, emit (alpha, beta).
// pass3: fold pp_in and aa_in, replay chunk exactly as reference, write out.
// ---------------------------------------------------------------------------
__global__ void __launch_bounds__(256) wkv_p1(
    const float* __restrict__ kp, const float* __restrict__ wdec,
    float* __restrict__ ppl)
{
    int gid = blockIdx.x * 256 + threadIdx.x;   // 0..131071
    int c  = gid & (CC - 1);
    int ch = (gid >> 10) & (NCH - 1);
    int b  = gid >> 14;
    float w = wdec[c];
    float pp = -1e38f;
    size_t idx = ((size_t)b * TT + (size_t)ch * CHL) * CC + c;
    #pragma unroll 2
    for (int t = 0; t < CHL; t++, idx += CC) {
        float kk = kp[idx];
        float pw = pp + w, wk = w + kk;
        float p2 = fmaxf(pw, wk);
        pp = p2 + __logf(__expf(pw - p2) + __expf(wk - p2));
    }
    ppl[((size_t)b * NCH + ch) * CC + c] = pp;
}

__device__ __forceinline__ float fold_pp(
    const float* __restrict__ ppl, int b, int c, int ch, float Lw)
{
    float pin = -1e38f;
    for (int j = 0; j < ch; j++) {
        float a  = pin + Lw;
        float pl = ppl[((size_t)b * NCH + j) * CC + c];
        float m  = fmaxf(a, pl);
        pin = m + __logf(__expf(a - m) + __expf(pl - m));
    }
    return pin;
}

__global__ void __launch_bounds__(256) wkv_p2(
    const float* __restrict__ kp, const float* __restrict__ vp,
    const float* __restrict__ wdec, const float* __restrict__ ppl,
    float* __restrict__ alp, float* __restrict__ bet)
{
    int gid = blockIdx.x * 256 + threadIdx.x;
    int c  = gid & (CC - 1);
    int ch = (gid >> 10) & (NCH - 1);
    int b  = gid >> 14;
    float w = wdec[c];
    float pp = fold_pp(ppl, b, c, ch, (float)CHL * w);
    float alpha = 1.0f, beta = 0.0f;
    size_t idx = ((size_t)b * TT + (size_t)ch * CHL) * CC + c;
    #pragma unroll 2
    for (int t = 0; t < CHL; t++, idx += CC) {
        float kk = kp[idx], vv = vp[idx];
        float pw = pp + w, wk = w + kk;
        float p2 = fmaxf(pw, wk);
        float e1u = __expf(pw - p2);
        float e2u = __expf(wk - p2);
        alpha *= e1u;
        beta = e1u * beta + e2u * vv;
        pp = p2 + __logf(e1u + e2u);
    }
    size_t o = ((size_t)b * NCH + ch) * CC + c;
    alp[o] = alpha;
    bet[o] = beta;
}

__global__ void __launch_bounds__(256) wkv_p3(
    const float* __restrict__ kp, const float* __restrict__ vp,
    const float* __restrict__ rp, const float* __restrict__ xp,
    const float* __restrict__ wdec, const float* __restrict__ ufst,
    const float* __restrict__ ppl, const float* __restrict__ alp,
    const float* __restrict__ bet, float* __restrict__ out)
{
    int gid = blockIdx.x * 256 + threadIdx.x;
    int c  = gid & (CC - 1);
    int ch = (gid >> 10) & (NCH - 1);
    int b  = gid >> 14;
    float w = wdec[c], u = ufst[c];
    float pp = fold_pp(ppl, b, c, ch, (float)CHL * w);
    float aa = 0.0f;
    for (int j = 0; j < ch; j++) {
        size_t o = ((size_t)b * NCH + j) * CC + c;
        aa = alp[o] * aa + bet[o];
    }
    size_t idx = ((size_t)b * TT + (size_t)ch * CHL) * CC + c;
    #pragma unroll 2
    for (int t = 0; t < CHL; t++, idx += CC) {
        float kk = kp[idx];
        float vv = vp[idx];
        float rr = rp[idx];
        float xx = xp[idx];
        float uk = u + kk;
        float p  = fmaxf(pp, uk);
        float e1 = __expf(pp - p);
        float e2 = __expf(uk - p);
        float y  = (e1 * aa + e2 * vv) / (e1 + e2);
        out[idx] = xx + rr * y;
        float pw = pp + w;
        float wk = w + kk;
        float p2 = fmaxf(pw, wk);
        float e1u = __expf(pw - p2);
        float e2u = __expf(wk - p2);
        aa = e1u * aa + e2u * vv;
        pp = p2 + __logf(e1u + e2u);
    }
}

// ---------------------------------------------------------------------------
// Weight transpose + fp16 RN: src[R,Ccols] fp32 -> dst[Ccols,R] fp16
// ---------------------------------------------------------------------------
__global__ void __launch_bounds__(256) thalf_kernel(
    const float* __restrict__ src, __half* __restrict__ dst, int R, int Ccols)
{
    __shared__ float t[32][33];
    int r0 = blockIdx.y * 32, c0 = blockIdx.x * 32;
    int tx = threadIdx.x, ty = threadIdx.y;
    #pragma unroll
    for (int j = 0; j < 32; j += 8)
        t[ty + j][tx] = src[(size_t)(r0 + ty + j) * Ccols + c0 + tx];
    __syncthreads();
    #pragma unroll
    for (int j = 0; j < 32; j += 8)
        dst[(size_t)(c0 + ty + j) * R + r0 + tx] = __float2half_rn(t[tx][ty + j]);
}

// ---------------------------------------------------------------------------
// fp16 single-pass GEMM core: C[M,N] = epi(A[M,K] @ Bt[N,K]^T), fp32 accum.
// CTA tile 256x128, k-step 16, 4-stage cp.async pipeline, ldmatrix frags.
// phys(row, c) = (row>>3)*256 + ((c<<3 | (row&7))<<4), c = k-half (0/1).
// ---------------------------------------------------------------------------
#define CTM 256
#define CTN 128
#define ST_A 8192
#define STAGE_BYTES 12288
#define GSMEM (STAGE_BYTES*4)   // 49152

#define EPI_NONE 0
#define EPI_SIGMOID 1
#define EPI_RELUSQ 2
#define EPI_RESID 3

template<int EPI>
__device__ __forceinline__ void gemm_core(
    const __half* __restrict__ A, const __half* __restrict__ Bt,
    int K, int m0, int n0B,
    float* __restrict__ outF, const float* __restrict__ resid,
    const float* __restrict__ gate,
    __half* __restrict__ outH, int Nout, int n0o)
{
    extern __shared__ char smem[];
    const uint32_t sbase = smem_u32(smem);
    const int tid = threadIdx.x;
    const int lane = tid & 31, wid = tid >> 5;
    const int wm = wid & 3, wn = wid >> 2;
    const int NS = K >> 4;

    auto load_stage = [&](int s, int buf){
        const int k0 = s << 4;
        uint32_t st = sbase + (uint32_t)buf * STAGE_BYTES;
        #pragma unroll
        for (int l = 0; l < 2; l++) {
            int chk = l*256 + tid;                  // 0..511
            int row = chk >> 1, c = chk & 1;
            uint32_t d = (uint32_t)((row>>3)<<8) | (uint32_t)((((c<<3)|(row&7)))<<4);
            cp16(st + d, A + (size_t)(m0+row)*K + k0 + c*8);
        }
        {
            int row = tid >> 1, c = tid & 1;        // 0..255 chunks
            uint32_t d = (uint32_t)((row>>3)<<8) | (uint32_t)((((c<<3)|(row&7)))<<4);
            cp16(st + ST_A + d, Bt + (size_t)(n0B+row)*K + k0 + c*8);
        }
    };

    float acc[4][8][4];
    #pragma unroll
    for (int mi = 0; mi < 4; mi++)
        #pragma unroll
        for (int ni = 0; ni < 8; ni++)
            #pragma unroll
            for (int c = 0; c < 4; c++) acc[mi][ni][c] = 0.0f;

    load_stage(0, 0); CP_COMMIT();
    load_stage(1, 1); CP_COMMIT();
    load_stage(2, 2); CP_COMMIT();

    const int rl = lane & 15, chh = lane >> 4;
    const uint32_t bpart = (uint32_t)(((rl>>3)<<8) | (((chh<<3)|(rl&7))<<4));

    for (int s = 0; s < NS; s++) {
        int buf = s & 3;
        CP_WAIT2();
        __syncthreads();
        if (s + 3 < NS) load_stage(s + 3, (s + 3) & 3);
        CP_COMMIT();

        uint32_t stA = sbase + (uint32_t)buf * STAGE_BYTES;
        uint32_t stB = stA + ST_A;

        uint32_t a[4][4], b[8][2];
        #pragma unroll
        for (int mi = 0; mi < 4; mi++) {
            uint32_t ad = stA + (uint32_t)((wm*8 + mi*2) << 8) + bpart;
            LDSM4(a[mi][0], a[mi][1], a[mi][2], a[mi][3], ad);
        }
        #pragma unroll
        for (int g = 0; g < 4; g++) {
            uint32_t bd = stB + (uint32_t)((wn*8 + g*2) << 8) + bpart;
            uint32_t r0, r1, r2, r3;
            LDSM4(r0, r1, r2, r3, bd);
            b[2*g][0] = r0;   b[2*g][1] = r2;
            b[2*g+1][0] = r1; b[2*g+1][1] = r3;
        }
        #pragma unroll
        for (int mi = 0; mi < 4; mi++)
            #pragma unroll
            for (int ni = 0; ni < 8; ni++)
                mma16816(acc[mi][ni], a[mi], b[ni]);
    }

    // ---- epilogue
    #pragma unroll
    for (int mi = 0; mi < 4; mi++) {
        int r0 = m0 + wm*64 + mi*16 + (lane >> 2);
        #pragma unroll
        for (int ni = 0; ni < 8; ni++) {
            int c0 = n0o + wn*64 + ni*8 + (lane & 3)*2;
            float v0 = acc[mi][ni][0], v1 = acc[mi][ni][1];
            float v2 = acc[mi][ni][2], v3 = acc[mi][ni][3];
            size_t i0 = (size_t)r0 * Nout + c0;
            size_t i1 = (size_t)(r0 + 8) * Nout + c0;
            if (EPI == EPI_SIGMOID) {
                v0 = 1.f/(1.f+__expf(-v0)); v1 = 1.f/(1.f+__expf(-v1));
                v2 = 1.f/(1.f+__expf(-v2)); v3 = 1.f/(1.f+__expf(-v3));
            } else if (EPI == EPI_RELUSQ) {
                v0 = fmaxf(v0,0.f); v1 = fmaxf(v1,0.f);
                v2 = fmaxf(v2,0.f); v3 = fmaxf(v3,0.f);
                *(__half2*)(outH + i0) = __floats2half2_rn(v0*v0, v1*v1);
                *(__half2*)(outH + i1) = __floats2half2_rn(v2*v2, v3*v3);
                continue;
            }
            if (EPI == EPI_RESID) {
                float2 rz0 = *(const float2*)(resid + i0);
                float2 rz1 = *(const float2*)(resid + i1);
                float2 gz0 = *(const float2*)(gate  + i0);
                float2 gz1 = *(const float2*)(gate  + i1);
                v0 = rz0.x + gz0.x*v0; v1 = rz0.y + gz0.y*v1;
                v2 = rz1.x + gz1.x*v2; v3 = rz1.y + gz1.y*v3;
            }
            *(float2*)(outF + i0) = make_float2(v0, v1);
            *(float2*)(outF + i1) = make_float2(v2, v3);
        }
    }
}

// Fused k|v|r GEMM: N-blocks 0-7 -> k, 8-15 -> v, 16-23 -> sigmoid r
__global__ void __launch_bounds__(256, 1) gemm_kvr(
    const __half* xk, const __half* xv, const __half* xr,
    const __half* Bt, float* outk, float* outv, float* outr)
{
    int seg = blockIdx.x >> 3;
    int m0  = blockIdx.y * CTM;
    int n0B = blockIdx.x * CTN;
    int n0o = (blockIdx.x & 7) * CTN;
    const __half* Aa = (seg == 0) ? xk : (seg == 1) ? xv : xr;
    float* o = (seg == 0) ? outk : (seg == 1) ? outv : outr;
    if (seg == 2)
        gemm_core<EPI_SIGMOID>(Aa, Bt, CC, m0, n0B, o, nullptr, nullptr, nullptr, CC, n0o);
    else
        gemm_core<EPI_NONE>(Aa, Bt, CC, m0, n0B, o, nullptr, nullptr, nullptr, CC, n0o);
}

// Fused kk|s GEMM: N-blocks 0-31 -> relu^2 kk (fp16), 32-39 -> sigmoid s
__global__ void __launch_bounds__(256, 1) gemm_cks(
    const __half* ck, const __half* cr, const __half* Bt,
    __half* kk, float* outs)
{
    int bx = blockIdx.x;
    int m0 = blockIdx.y * CTM;
    int n0B = bx * CTN;
    if (bx < 32)
        gemm_core<EPI_RELUSQ>(ck, Bt, CC, m0, n0B, nullptr, nullptr, nullptr, kk, 4*CC, bx*CTN);
    else
        gemm_core<EPI_SIGMOID>(cr, Bt, CC, m0, n0B, outs, nullptr, nullptr, nullptr, CC, (bx-32)*CTN);
}

// Final GEMM: out = x2 + s * (kk @ w_cv), K = 4096
__global__ void __launch_bounds__(256, 1) gemm_out(
    const __half* kk, const __half* Bt,
    float* out, const float* x2, const float* sg)
{
    int m0 = blockIdx.y * CTM;
    int n0 = blockIdx.x * CTN;
    gemm_core<EPI_RESID>(kk, Bt, 4*CC, m0, n0, out, x2, sg, nullptr, CC, n0);
}

// ---------------------------------------------------------------------------
// Host launcher
// ---------------------------------------------------------------------------
template<typename T>
static T* symaddr(const void* sym)
{
    void* p = nullptr;
    cudaGetSymbolAddress(&p, sym);
    return (T*)p;
}

extern "C" void kernel_launch(void* const* d_in, const int* in_sizes, int n_in,
                              void* d_out, int out_size)
{
    const float* x      = (const float*)d_in[0];
    const float* tdecay = (const float*)d_in[1];
    const float* tfirst = (const float*)d_in[2];
    const float* w_tk   = (const float*)d_in[3];
    const float* w_tv   = (const float*)d_in[4];
    const float* w_tr   = (const float*)d_in[5];
    const float* w_ck   = (const float*)d_in[6];
    const float* w_cv   = (const float*)d_in[7];
    const float* w_cr   = (const float*)d_in[8];
    const float* ln1_g  = (const float*)d_in[9];
    const float* ln1_b  = (const float*)d_in[10];
    const float* ln2_g  = (const float*)d_in[11];
    const float* ln2_b  = (const float*)d_in[12];
    const float* mix_k  = (const float*)d_in[13];
    const float* mix_v  = (const float*)d_in[14];
    const float* mix_r  = (const float*)d_in[15];
    const float* cmix_k = (const float*)d_in[16];
    const float* cmix_r = (const float*)d_in[17];
    float* out = (float*)d_out;

    float* h   = symaddr<float>(g_h);
    float* k   = symaddr<float>(g_k);
    float* v   = symaddr<float>(g_v);
    float* r   = symaddr<float>(g_r);
    float* x2  = symaddr<float>(g_x2);
    float* h2  = symaddr<float>(g_h2);
    float* s   = symaddr<float>(g_s);
    float* ppl = symaddr<float>(g_ppl);
    float* alp = symaddr<float>(g_alp);
    float* bet = symaddr<float>(g_bet);
    __half* xk = symaddr<__half>(g_xk);
    __half* xv = symaddr<__half>(g_xv);
    __half* xr = symaddr<__half>(g_xr);
    __half* ck = symaddr<__half>(g_ck);
    __half* cr = symaddr<__half>(g_cr);
    __half* kk = symaddr<__half>(g_kk);
    __half* wkvr = symaddr<__half>(g_wkvr);
    __half* wcks = symaddr<__half>(g_wcks);
    __half* wcv  = symaddr<__half>(g_wcv);

    cudaFuncSetAttribute((const void*)gemm_kvr, cudaFuncAttributeMaxDynamicSharedMemorySize, GSMEM);
    cudaFuncSetAttribute((const void*)gemm_cks, cudaFuncAttributeMaxDynamicSharedMemorySize, GSMEM);
    cudaFuncSetAttribute((const void*)gemm_out, cudaFuncAttributeMaxDynamicSharedMemorySize, GSMEM);

    const int M = MROWS;
    dim3 tb(32, 8);
    const int mixg = (BTC/4) / 256;
    const int wkvg = (MB * CC * NCH) / 256;   // 512 blocks

    // 0-2) transpose+fp16 time-mix weights into concat buffer [3072,1024]
    thalf_kernel<<<dim3(CC/32, CC/32), tb>>>(w_tk, wkvr,           CC, CC);
    thalf_kernel<<<dim3(CC/32, CC/32), tb>>>(w_tv, wkvr + CC*CC,   CC, CC);
    thalf_kernel<<<dim3(CC/32, CC/32), tb>>>(w_tr, wkvr + 2*CC*CC, CC, CC);

    // 3) h = LN1(x);  4) token-shift mixes (fp16)
    ln_kernel<<<M, 256>>>(x, ln1_g, ln1_b, h);
    mix3_kernel<<<mixg, 256>>>(h, mix_k, mix_v, mix_r, xk, xv, xr);

    // 5) fused k|v|r GEMM
    gemm_kvr<<<dim3(24, M/CTM), 256, GSMEM>>>(xk, xv, xr, wkvr, k, v, r);

    // 6) x2 = x + r * WKV(k, v)  — chunked 3-pass scan
    wkv_p1<<<wkvg, 256>>>(k, tdecay, ppl);
    wkv_p2<<<wkvg, 256>>>(k, v, tdecay, ppl, alp, bet);
    wkv_p3<<<wkvg, 256>>>(k, v, r, x, tdecay, tfirst, ppl, alp, bet, x2);

    // 7) h2 = LN2(x2);  8) channel mixes
    ln_kernel<<<M, 256>>>(x2, ln2_g, ln2_b, h2);
    mix2_kernel<<<mixg, 256>>>(h2, cmix_k, cmix_r, ck, cr);

    // 9-11) transpose+fp16 channel weights: concat [5120,1024] and [1024,4096]
    thalf_kernel<<<dim3(4*CC/32, CC/32), tb>>>(w_ck, wcks,           CC, 4*CC);
    thalf_kernel<<<dim3(CC/32, CC/32),   tb>>>(w_cr, wcks + 4*CC*CC, CC, CC);
    thalf_kernel<<<dim3(CC/32, 4*CC/32), tb>>>(w_cv, wcv,            4*CC, CC);

    // 12) fused kk|s GEMM: kk = relu(ck@w_ck)^2 (fp16), s = sigmoid(cr@w_cr)
    gemm_cks<<<dim3(40, M/CTM), 256, GSMEM>>>(ck, cr, wcks, kk, s);

    // 13) out = x2 + s * (kk @ w_cv), K = 4096
    gemm_out<<<dim3(8, M/CTM), 256, GSMEM>>>(kk, wcv, out, x2, s);
}

// round 15
// speedup vs baseline: 4.2376x; 1.1591x over previous
#include <cuda_runtime.h>
#include <cuda_fp16.h>
#include <cstdint>
#include <cstddef>

// Problem constants
#define MB 8
#define TT 2048
#define CC 1024
#define MROWS (MB*TT)          // 16384
#define BTC (MROWS*CC)
#define BT4C (MROWS*4*CC)
#define NCH 16
#define CHL (TT/NCH)           // 128

// fp32 scratch
__device__ float g_h [BTC];
__device__ float g_k [BTC];
__device__ float g_v [BTC];
__device__ float g_r [BTC];
__device__ float g_x2[BTC];
__device__ float g_h2[BTC];
__device__ float g_s [BTC];
// WKV chunk aggregates: layout [b][chunk][c]
__device__ float g_ppl[MB*NCH*CC];
__device__ float g_alp[MB*NCH*CC];
__device__ float g_bet[MB*NCH*CC];
// fp16 operand scratch
__device__ __half g_xk[BTC];
__device__ __half g_xv[BTC];
__device__ __half g_xr[BTC];
__device__ __half g_ck[BTC];
__device__ __half g_cr[BTC];
__device__ __half g_kk[BT4C];
__device__ __half g_wkvr[3*CC*CC];   // wtkT | wtvT | wtrT  (K-major fp16)
__device__ __half g_wcks[5*CC*CC];   // wckT | wcrT
__device__ __half g_wcv [4*CC*CC];   // wcvT

// ---------------------------------------------------------------------------
// Helpers
// ---------------------------------------------------------------------------
__device__ __forceinline__ uint32_t smem_u32(const void* p){
    uint32_t a;
    asm("{ .reg .u64 t; cvta.to.shared.u64 t, %1; cvt.u32.u64 %0, t; }" : "=r"(a) : "l"(p));
    return a;
}
__device__ __forceinline__ void cp16(uint32_t dst, const void* src){
    asm volatile("cp.async.ca.shared.global [%0], [%1], 16;" :: "r"(dst), "l"(src));
}
#define CP_COMMIT() asm volatile("cp.async.commit_group;" ::: "memory")
#define CP_WAIT2()  asm volatile("cp.async.wait_group 2;" ::: "memory")
#define CP_WAIT3()  asm volatile("cp.async.wait_group 3;" ::: "memory")
#define LDSM4(r0,r1,r2,r3,a) \
    asm volatile("ldmatrix.sync.aligned.m8n8.x4.shared.b16 {%0,%1,%2,%3}, [%4];" \
        : "=r"(r0),"=r"(r1),"=r"(r2),"=r"(r3) : "r"(a))

__device__ __forceinline__ void mma16816(float* d, const uint32_t* a, const uint32_t* b){
    asm volatile("mma.sync.aligned.m16n8k16.row.col.f32.f16.f16.f32 "
        "{%0,%1,%2,%3}, {%4,%5,%6,%7}, {%8,%9}, {%0,%1,%2,%3};"
        : "+f"(d[0]), "+f"(d[1]), "+f"(d[2]), "+f"(d[3])
        : "r"(a[0]), "r"(a[1]), "r"(a[2]), "r"(a[3]), "r"(b[0]), "r"(b[1]));
}

__device__ __forceinline__ void h4store(float4 v, __half* p){
    __half2* P = (__half2*)p;
    P[0] = __floats2half2_rn(v.x, v.y);
    P[1] = __floats2half2_rn(v.z, v.w);
}

// ---------------------------------------------------------------------------
// LayerNorm: one 256-thread block per row of C=1024 (fp32 out)
// ---------------------------------------------------------------------------
__global__ void __launch_bounds__(256) ln_kernel(
    const float* __restrict__ x, const float* __restrict__ g,
    const float* __restrict__ b, float* __restrict__ out)
{
    const int C = CC;
    size_t row = blockIdx.x;
    const float4* xr = (const float4*)(x + row * C);
    int tid = threadIdx.x;
    float4 v = xr[tid];

    float s = v.x + v.y + v.z + v.w;
    #pragma unroll
    for (int o = 16; o > 0; o >>= 1) s += __shfl_xor_sync(0xffffffffu, s, o);
    __shared__ float ws[8];
    if ((tid & 31) == 0) ws[tid >> 5] = s;
    __syncthreads();
    float mu = (ws[0]+ws[1]+ws[2]+ws[3]+ws[4]+ws[5]+ws[6]+ws[7]) * (1.0f / C);
    __syncthreads();

    float dx = v.x - mu, dy = v.y - mu, dz = v.z - mu, dw = v.w - mu;
    float s2 = dx*dx + dy*dy + dz*dz + dw*dw;
    #pragma unroll
    for (int o = 16; o > 0; o >>= 1) s2 += __shfl_xor_sync(0xffffffffu, s2, o);
    if ((tid & 31) == 0) ws[tid >> 5] = s2;
    __syncthreads();
    float var = (ws[0]+ws[1]+ws[2]+ws[3]+ws[4]+ws[5]+ws[6]+ws[7]) * (1.0f / C);
    float rstd = rsqrtf(var + 1e-5f);

    float4 gv = ((const float4*)g)[tid];
    float4 bv = ((const float4*)b)[tid];
    float4 o;
    o.x = dx * rstd * gv.x + bv.x;
    o.y = dy * rstd * gv.y + bv.y;
    o.z = dz * rstd * gv.z + bv.z;
    o.w = dw * rstd * gv.w + bv.w;
    ((float4*)(out + row * C))[tid] = o;
}

// ---------------------------------------------------------------------------
// Token-shift mixes -> fp16 operand arrays
// ---------------------------------------------------------------------------
__device__ __forceinline__ float4 mixf4(float4 h, float4 hp, float4 m){
    float4 o;
    o.x = h.x*m.x + hp.x*(1.f-m.x);
    o.y = h.y*m.y + hp.y*(1.f-m.y);
    o.z = h.z*m.z + hp.z*(1.f-m.z);
    o.w = h.w*m.w + hp.w*(1.f-m.w);
    return o;
}
__global__ void __launch_bounds__(256) mix3_kernel(
    const float* __restrict__ h, const float* __restrict__ mk,
    const float* __restrict__ mv, const float* __restrict__ mr,
    __half* xk, __half* xv, __half* xr)
{
    int j = blockIdx.x * 256 + threadIdx.x;   // float4 index
    int row = j >> 8;
    int c4  = j & 255;
    float4 hv = ((const float4*)h)[j];
    float4 hp = make_float4(0.f,0.f,0.f,0.f);
    if ((row & (TT-1)) != 0) hp = ((const float4*)h)[j - 256];
    h4store(mixf4(hv, hp, ((const float4*)mk)[c4]), xk + j*4);
    h4store(mixf4(hv, hp, ((const float4*)mv)[c4]), xv + j*4);
    h4store(mixf4(hv, hp, ((const float4*)mr)[c4]), xr + j*4);
}
__global__ void __launch_bounds__(256) mix2_kernel(
    const float* __restrict__ h, const float* __restrict__ mk,
    const float* __restrict__ mr, __half* ck, __half* cr)
{
    int j = blockIdx.x * 256 + threadIdx.x;
    int row = j >> 8;
    int c4  = j & 255;
    float4 hv = ((const float4*)h)[j];
    float4 hp = make_float4(0.f,0.f,0.f,0.f);
    if ((row & (TT-1)) != 0) hp = ((const float4*)h)[j - 256];
    h4store(mixf4(hv, hp, ((const float4*)mk)[c4]), ck + j*4);
    h4store(mixf4(hv, hp, ((const float4*)mr)[c4]), cr + j*4);
}

// ---------------------------------------------------------------------------
// WKV chunked 3-pass scan (R12 proven version).
//   pp_t = log P_t, P' = e^w(P + e^k)  -> LSE-associative.
//   Given the pp path, aa' = e1u*aa + e2u*v is affine in aa_in:
//     alpha = prod(e1u), beta = aa from zero init — computed with the TRUE
//     incoming pp (fold first), since the pp path shapes e1u/e2u.
// ---------------------------------------------------------------------------
__global__ void __launch_bounds__(256) wkv_p1(
    const float* __restrict__ kp, const float* __restrict__ wdec,
    float* __restrict__ ppl)
{
    int gid = blockIdx.x * 256 + threadIdx.x;   // 0..131071
    int c  = gid & (CC - 1);
    int ch = (gid >> 10) & (NCH - 1);
    int b  = gid >> 14;
    float w = wdec[c];
    float pp = -1e38f;
    size_t idx = ((size_t)b * TT + (size_t)ch * CHL) * CC + c;
    #pragma unroll 2
    for (int t = 0; t < CHL; t++, idx += CC) {
        float kk = kp[idx];
        float pw = pp + w, wk = w + kk;
        float p2 = fmaxf(pw, wk);
        pp = p2 + __logf(__expf(pw - p2) + __expf(wk - p2));
    }
    ppl[((size_t)b * NCH + ch) * CC + c] = pp;
}

__device__ __forceinline__ float fold_pp(
    const float* __restrict__ ppl, int b, int c, int ch, float Lw)
{
    float pin = -1e38f;
    for (int j = 0; j < ch; j++) {
        float a  = pin + Lw;
        float pl = ppl[((size_t)b * NCH + j) * CC + c];
        float m  = fmaxf(a, pl);
        pin = m + __logf(__expf(a - m) + __expf(pl - m));
    }
    return pin;
}

__global__ void __launch_bounds__(256) wkv_p2(
    const float* __restrict__ kp, const float* __restrict__ vp,
    const float* __restrict__ wdec, const float* __restrict__ ppl,
    float* __restrict__ alp, float* __restrict__ bet)
{
    int gid = blockIdx.x * 256 + threadIdx.x;
    int c  = gid & (CC - 1);
    int ch = (gid >> 10) & (NCH - 1);
    int b  = gid >> 14;
    float w = wdec[c];
    float pp = fold_pp(ppl, b, c, ch, (float)CHL * w);
    float alpha = 1.0f, beta = 0.0f;
    size_t idx = ((size_t)b * TT + (size_t)ch * CHL) * CC + c;
    #pragma unroll 2
    for (int t = 0; t < CHL; t++, idx += CC) {
        float kk = kp[idx], vv = vp[idx];
        float pw = pp + w, wk = w + kk;
        float p2 = fmaxf(pw, wk);
        float e1u = __expf(pw - p2);
        float e2u = __expf(wk - p2);
        alpha *= e1u;
        beta = e1u * beta + e2u * vv;
        pp = p2 + __logf(e1u + e2u);
    }
    size_t o = ((size_t)b * NCH + ch) * CC + c;
    alp[o] = alpha;
    bet[o] = beta;
}

__global__ void __launch_bounds__(256) wkv_p3(
    const float* __restrict__ kp, const float* __restrict__ vp,
    const float* __restrict__ rp, const float* __restrict__ xp,
    const float* __restrict__ wdec, const float* __restrict__ ufst,
    const float* __restrict__ ppl, const float* __restrict__ alp,
    const float* __restrict__ bet, float* __restrict__ out)
{
    int gid = blockIdx.x * 256 + threadIdx.x;
    int c  = gid & (CC - 1);
    int ch = (gid >> 10) & (NCH - 1);
    int b  = gid >> 14;
    float w = wdec[c], u = ufst[c];
    float pp = fold_pp(ppl, b, c, ch, (float)CHL * w);
    float aa = 0.0f;
    for (int j = 0; j < ch; j++) {
        size_t o = ((size_t)b * NCH + j) * CC + c;
        aa = alp[o] * aa + bet[o];
    }
    size_t idx = ((size_t)b * TT + (size_t)ch * CHL) * CC + c;
    #pragma unroll 2
    for (int t = 0; t < CHL; t++, idx += CC) {
        float kk = kp[idx];
        float vv = vp[idx];
        float rr = rp[idx];
        float xx = xp[idx];
        float uk = u + kk;
        float p  = fmaxf(pp, uk);
        float e1 = __expf(pp - p);
        float e2 = __expf(uk - p);
        float y  = (e1 * aa + e2 * vv) / (e1 + e2);
        out[idx] = xx + rr * y;
        float pw = pp + w;
        float wk = w + kk;
        float p2 = fmaxf(pw, wk);
        float e1u = __expf(pw - p2);
        float e2u = __expf(wk - p2);
        aa = e1u * aa + e2u * vv;
        pp = p2 + __logf(e1u + e2u);
    }
}

// ---------------------------------------------------------------------------
// Weight transpose + fp16 RN: src[R,Ccols] fp32 -> dst[Ccols,R] fp16
// ---------------------------------------------------------------------------
__global__ void __launch_bounds__(256) thalf_kernel(
    const float* __restrict__ src, __half* __restrict__ dst, int R, int Ccols)
{
    __shared__ float t[32][33];
    int r0 = blockIdx.y * 32, c0 = blockIdx.x * 32;
    int tx = threadIdx.x, ty = threadIdx.y;
    #pragma unroll
    for (int j = 0; j < 32; j += 8)
        t[ty + j][tx] = src[(size_t)(r0 + ty + j) * Ccols + c0 + tx];
    __syncthreads();
    #pragma unroll
    for (int j = 0; j < 32; j += 8)
        dst[(size_t)(c0 + ty + j) * R + r0 + tx] = __float2half_rn(t[tx][ty + j]);
}

// ---------------------------------------------------------------------------
// fp16 single-pass GEMM core with cross-stage fragment double-buffering:
// after each barrier, LDSM for stage s+1 issues BEFORE the MMAs of stage s,
// so the tensor pipe runs while fragment loads drain.
// C[M,N] = epi(A[M,K] @ Bt[N,K]^T), fp32 accum.
// CTA tile 256x128, k-step 16, 4 committed cp.async stages.
// phys(row, c) = (row>>3)*256 + ((c<<3 | (row&7))<<4), c = k-half (0/1).
// ---------------------------------------------------------------------------
#define CTM 256
#define CTN 128
#define ST_A 8192
#define STAGE_BYTES 12288
#define GSMEM (STAGE_BYTES*4)   // 49152

#define EPI_NONE 0
#define EPI_SIGMOID 1
#define EPI_RELUSQ 2
#define EPI_RESID 3

template<int EPI>
__device__ __forceinline__ void gemm_core(
    const __half* __restrict__ A, const __half* __restrict__ Bt,
    int K, int m0, int n0B,
    float* __restrict__ outF, const float* __restrict__ resid,
    const float* __restrict__ gate,
    __half* __restrict__ outH, int Nout, int n0o)
{
    extern __shared__ char smem[];
    const uint32_t sbase = smem_u32(smem);
    const int tid = threadIdx.x;
    const int lane = tid & 31, wid = tid >> 5;
    const int wm = wid & 3, wn = wid >> 2;
    const int NS = K >> 4;

    auto load_stage = [&](int s, int buf){
        const int k0 = s << 4;
        uint32_t st = sbase + (uint32_t)buf * STAGE_BYTES;
        #pragma unroll
        for (int l = 0; l < 2; l++) {
            int chk = l*256 + tid;                  // 0..511
            int row = chk >> 1, c = chk & 1;
            uint32_t d = (uint32_t)((row>>3)<<8) | (uint32_t)((((c<<3)|(row&7)))<<4);
            cp16(st + d, A + (size_t)(m0+row)*K + k0 + c*8);
        }
        {
            int row = tid >> 1, c = tid & 1;        // 0..255 chunks
            uint32_t d = (uint32_t)((row>>3)<<8) | (uint32_t)((((c<<3)|(row&7)))<<4);
            cp16(st + ST_A + d, Bt + (size_t)(n0B+row)*K + k0 + c*8);
        }
    };

    const int rl = lane & 15, chh = lane >> 4;
    const uint32_t bpart = (uint32_t)(((rl>>3)<<8) | (((chh<<3)|(rl&7))<<4));

    auto ldsm_stage = [&](int buf, uint32_t a[4][4], uint32_t b[8][2]){
        uint32_t stA = sbase + (uint32_t)buf * STAGE_BYTES;
        uint32_t stB = stA + ST_A;
        #pragma unroll
        for (int mi = 0; mi < 4; mi++) {
            uint32_t ad = stA + (uint32_t)((wm*8 + mi*2) << 8) + bpart;
            LDSM4(a[mi][0], a[mi][1], a[mi][2], a[mi][3], ad);
        }
        #pragma unroll
        for (int g = 0; g < 4; g++) {
            uint32_t bd = stB + (uint32_t)((wn*8 + g*2) << 8) + bpart;
            uint32_t r0, r1, r2, r3;
            LDSM4(r0, r1, r2, r3, bd);
            b[2*g][0] = r0;   b[2*g][1] = r2;
            b[2*g+1][0] = r1; b[2*g+1][1] = r3;
        }
    };

    float acc[4][8][4];
    #pragma unroll
    for (int mi = 0; mi < 4; mi++)
        #pragma unroll
        for (int ni = 0; ni < 8; ni++)
            #pragma unroll
            for (int c = 0; c < 4; c++) acc[mi][ni][c] = 0.0f;

    load_stage(0, 0); CP_COMMIT();
    load_stage(1, 1); CP_COMMIT();
    load_stage(2, 2); CP_COMMIT();
    load_stage(3, 3); CP_COMMIT();

    uint32_t af[2][4][4], bf[2][8][2];
    CP_WAIT3();
    __syncthreads();
    ldsm_stage(0, af[0], bf[0]);

    #pragma unroll 2
    for (int s = 0; s < NS; s++) {
        const int pc = s & 1, pn = pc ^ 1;
        CP_WAIT2();            // groups complete in order -> stage s+1 arrived
        __syncthreads();       // cross-thread visibility; buf s&3 fully consumed
        if (s + 4 < NS) load_stage(s + 4, s & 3);
        CP_COMMIT();
        if (s + 1 < NS) ldsm_stage((s + 1) & 3, af[pn], bf[pn]);
        #pragma unroll
        for (int mi = 0; mi < 4; mi++)
            #pragma unroll
            for (int ni = 0; ni < 8; ni++)
                mma16816(acc[mi][ni], af[pc][mi], bf[pc][ni]);
    }

    // ---- epilogue
    #pragma unroll
    for (int mi = 0; mi < 4; mi++) {
        int r0 = m0 + wm*64 + mi*16 + (lane >> 2);
        #pragma unroll
        for (int ni = 0; ni < 8; ni++) {
            int c0 = n0o + wn*64 + ni*8 + (lane & 3)*2;
            float v0 = acc[mi][ni][0], v1 = acc[mi][ni][1];
            float v2 = acc[mi][ni][2], v3 = acc[mi][ni][3];
            size_t i0 = (size_t)r0 * Nout + c0;
            size_t i1 = (size_t)(r0 + 8) * Nout + c0;
            if (EPI == EPI_SIGMOID) {
                v0 = 1.f/(1.f+__expf(-v0)); v1 = 1.f/(1.f+__expf(-v1));
                v2 = 1.f/(1.f+__expf(-v2)); v3 = 1.f/(1.f+__expf(-v3));
            } else if (EPI == EPI_RELUSQ) {
                v0 = fmaxf(v0,0.f); v1 = fmaxf(v1,0.f);
                v2 = fmaxf(v2,0.f); v3 = fmaxf(v3,0.f);
                *(__half2*)(outH + i0) = __floats2half2_rn(v0*v0, v1*v1);
                *(__half2*)(outH + i1) = __floats2half2_rn(v2*v2, v3*v3);
                continue;
            }
            if (EPI == EPI_RESID) {
                float2 rz0 = *(const float2*)(resid + i0);
                float2 rz1 = *(const float2*)(resid + i1);
                float2 gz0 = *(const float2*)(gate  + i0);
                float2 gz1 = *(const float2*)(gate  + i1);
                v0 = rz0.x + gz0.x*v0; v1 = rz0.y + gz0.y*v1;
                v2 = rz1.x + gz1.x*v2; v3 = rz1.y + gz1.y*v3;
            }
            *(float2*)(outF + i0) = make_float2(v0, v1);
            *(float2*)(outF + i1) = make_float2(v2, v3);
        }
    }
}

// Fused k|v|r GEMM: N-blocks 0-7 -> k, 8-15 -> v, 16-23 -> sigmoid r
__global__ void __launch_bounds__(256, 1) gemm_kvr(
    const __half* xk, const __half* xv, const __half* xr,
    const __half* Bt, float* outk, float* outv, float* outr)
{
    int seg = blockIdx.x >> 3;
    int m0  = blockIdx.y * CTM;
    int n0B = blockIdx.x * CTN;
    int n0o = (blockIdx.x & 7) * CTN;
    const __half* Aa = (seg == 0) ? xk : (seg == 1) ? xv : xr;
    float* o = (seg == 0) ? outk : (seg == 1) ? outv : outr;
    if (seg == 2)
        gemm_core<EPI_SIGMOID>(Aa, Bt, CC, m0, n0B, o, nullptr, nullptr, nullptr, CC, n0o);
    else
        gemm_core<EPI_NONE>(Aa, Bt, CC, m0, n0B, o, nullptr, nullptr, nullptr, CC, n0o);
}

// Fused kk|s GEMM: N-blocks 0-31 -> relu^2 kk (fp16), 32-39 -> sigmoid s
__global__ void __launch_bounds__(256, 1) gemm_cks(
    const __half* ck, const __half* cr, const __half* Bt,
    __half* kk, float* outs)
{
    int bx = blockIdx.x;
    int m0 = blockIdx.y * CTM;
    int n0B = bx * CTN;
    if (bx < 32)
        gemm_core<EPI_RELUSQ>(ck, Bt, CC, m0, n0B, nullptr, nullptr, nullptr, kk, 4*CC, bx*CTN);
    else
        gemm_core<EPI_SIGMOID>(cr, Bt, CC, m0, n0B, outs, nullptr, nullptr, nullptr, CC, (bx-32)*CTN);
}

// Final GEMM: out = x2 + s * (kk @ w_cv), K = 4096
__global__ void __launch_bounds__(256, 1) gemm_out(
    const __half* kk, const __half* Bt,
    float* out, const float* x2, const float* sg)
{
    int m0 = blockIdx.y * CTM;
    int n0 = blockIdx.x * CTN;
    gemm_core<EPI_RESID>(kk, Bt, 4*CC, m0, n0, out, x2, sg, nullptr, CC, n0);
}

// ---------------------------------------------------------------------------
// Host launcher
// ---------------------------------------------------------------------------
template<typename T>
static T* symaddr(const void* sym)
{
    void* p = nullptr;
    cudaGetSymbolAddress(&p, sym);
    return (T*)p;
}

extern "C" void kernel_launch(void* const* d_in, const int* in_sizes, int n_in,
                              void* d_out, int out_size)
{
    const float* x      = (const float*)d_in[0];
    const float* tdecay = (const float*)d_in[1];
    const float* tfirst = (const float*)d_in[2];
    const float* w_tk   = (const float*)d_in[3];
    const float* w_tv   = (const float*)d_in[4];
    const float* w_tr   = (const float*)d_in[5];
    const float* w_ck   = (const float*)d_in[6];
    const float* w_cv   = (const float*)d_in[7];
    const float* w_cr   = (const float*)d_in[8];
    const float* ln1_g  = (const float*)d_in[9];
    const float* ln1_b  = (const float*)d_in[10];
    const float* ln2_g  = (const float*)d_in[11];
    const float* ln2_b  = (const float*)d_in[12];
    const float* mix_k  = (const float*)d_in[13];
    const float* mix_v  = (const float*)d_in[14];
    const float* mix_r  = (const float*)d_in[15];
    const float* cmix_k = (const float*)d_in[16];
    const float* cmix_r = (const float*)d_in[17];
    float* out = (float*)d_out;

    float* h   = symaddr<float>(g_h);
    float* k   = symaddr<float>(g_k);
    float* v   = symaddr<float>(g_v);
    float* r   = symaddr<float>(g_r);
    float* x2  = symaddr<float>(g_x2);
    float* h2  = symaddr<float>(g_h2);
    float* s   = symaddr<float>(g_s);
    float* ppl = symaddr<float>(g_ppl);
    float* alp = symaddr<float>(g_alp);
    float* bet = symaddr<float>(g_bet);
    __half* xk = symaddr<__half>(g_xk);
    __half* xv = symaddr<__half>(g_xv);
    __half* xr = symaddr<__half>(g_xr);
    __half* ck = symaddr<__half>(g_ck);
    __half* cr = symaddr<__half>(g_cr);
    __half* kk = symaddr<__half>(g_kk);
    __half* wkvr = symaddr<__half>(g_wkvr);
    __half* wcks = symaddr<__half>(g_wcks);
    __half* wcv  = symaddr<__half>(g_wcv);

    cudaFuncSetAttribute((const void*)gemm_kvr, cudaFuncAttributeMaxDynamicSharedMemorySize, GSMEM);
    cudaFuncSetAttribute((const void*)gemm_cks, cudaFuncAttributeMaxDynamicSharedMemorySize, GSMEM);
    cudaFuncSetAttribute((const void*)gemm_out, cudaFuncAttributeMaxDynamicSharedMemorySize, GSMEM);

    const int M = MROWS;
    dim3 tb(32, 8);
    const int mixg = (BTC/4) / 256;
    const int wkvg = (MB * CC * NCH) / 256;   // 512 blocks

    // 0-2) transpose+fp16 time-mix weights into concat buffer [3072,1024]
    thalf_kernel<<<dim3(CC/32, CC/32), tb>>>(w_tk, wkvr,           CC, CC);
    thalf_kernel<<<dim3(CC/32, CC/32), tb>>>(w_tv, wkvr + CC*CC,   CC, CC);
    thalf_kernel<<<dim3(CC/32, CC/32), tb>>>(w_tr, wkvr + 2*CC*CC, CC, CC);

    // 3) h = LN1(x);  4) token-shift mixes (fp16)
    ln_kernel<<<M, 256>>>(x, ln1_g, ln1_b, h);
    mix3_kernel<<<mixg, 256>>>(h, mix_k, mix_v, mix_r, xk, xv, xr);

    // 5) fused k|v|r GEMM
    gemm_kvr<<<dim3(24, M/CTM), 256, GSMEM>>>(xk, xv, xr, wkvr, k, v, r);

    // 6) x2 = x + r * WKV(k, v)  — chunked 3-pass scan (R12 proven)
    wkv_p1<<<wkvg, 256>>>(k, tdecay, ppl);
    wkv_p2<<<wkvg, 256>>>(k, v, tdecay, ppl, alp, bet);
    wkv_p3<<<wkvg, 256>>>(k, v, r, x, tdecay, tfirst, ppl, alp, bet, x2);

    // 7) h2 = LN2(x2);  8) channel mixes
    ln_kernel<<<M, 256>>>(x2, ln2_g, ln2_b, h2);
    mix2_kernel<<<mixg, 256>>>(h2, cmix_k, cmix_r, ck, cr);

    // 9-11) transpose+fp16 channel weights: concat [5120,1024] and [1024,4096]
    thalf_kernel<<<dim3(4*CC/32, CC/32), tb>>>(w_ck, wcks,           CC, 4*CC);
    thalf_kernel<<<dim3(CC/32, CC/32),   tb>>>(w_cr, wcks + 4*CC*CC, CC, CC);
    thalf_kernel<<<dim3(CC/32, 4*CC/32), tb>>>(w_cv, wcv,            4*CC, CC);

    // 12) fused kk|s GEMM: kk = relu(ck@w_ck)^2 (fp16), s = sigmoid(cr@w_cr)
    gemm_cks<<<dim3(40, M/CTM), 256, GSMEM>>>(ck, cr, wcks, kk, s);

    // 13) out = x2 + s * (kk @ w_cv), K = 4096
    gemm_out<<<dim3(8, M/CTM), 256, GSMEM>>>(kk, wcv, out, x2, s);
}

// round 17
// speedup vs baseline: 4.2858x; 1.0114x over previous
#include <cuda_runtime.h>
#include <cuda_fp16.h>
#include <cstdint>
#include <cstddef>

// Problem constants
#define MB 8
#define TT 2048
#define CC 1024
#define MROWS (MB*TT)          // 16384
#define BTC (MROWS*CC)
#define BT4C (MROWS*4*CC)
#define NCH 16
#define CHL (TT/NCH)           // 128

// fp32 scratch
__device__ float g_k [BTC];
__device__ float g_v [BTC];
__device__ float g_r [BTC];
__device__ float g_x2[BTC];
__device__ float g_s [BTC];
// fp16 operand scratch
__device__ __half g_xk[BTC];
__device__ __half g_xv[BTC];
__device__ __half g_xr[BTC];
__device__ __half g_ck[BTC];
__device__ __half g_cr[BTC];
__device__ __half g_kk[BT4C];
__device__ __half g_wkvr[3*CC*CC];   // wtkT | wtvT | wtrT  (K-major fp16)
__device__ __half g_wcks[5*CC*CC];   // wckT | wcrT
__device__ __half g_wcv [4*CC*CC];   // wcvT

// ---------------------------------------------------------------------------
// Helpers
// ---------------------------------------------------------------------------
__device__ __forceinline__ uint32_t smem_u32(const void* p){
    uint32_t a;
    asm("{ .reg .u64 t; cvta.to.shared.u64 t, %1; cvt.u32.u64 %0, t; }" : "=r"(a) : "l"(p));
    return a;
}
__device__ __forceinline__ void cp16(uint32_t dst, const void* src){
    asm volatile("cp.async.ca.shared.global [%0], [%1], 16;" :: "r"(dst), "l"(src));
}
#define CP_COMMIT() asm volatile("cp.async.commit_group;" ::: "memory")
#define CP_WAIT2()  asm volatile("cp.async.wait_group 2;" ::: "memory")
#define CP_WAIT3()  asm volatile("cp.async.wait_group 3;" ::: "memory")
#define LDSM4(r0,r1,r2,r3,a) \
    asm volatile("ldmatrix.sync.aligned.m8n8.x4.shared.b16 {%0,%1,%2,%3}, [%4];" \
        : "=r"(r0),"=r"(r1),"=r"(r2),"=r"(r3) : "r"(a))

__device__ __forceinline__ void mma16816(float* d, const uint32_t* a, const uint32_t* b){
    asm volatile("mma.sync.aligned.m16n8k16.row.col.f32.f16.f16.f32 "
        "{%0,%1,%2,%3}, {%4,%5,%6,%7}, {%8,%9}, {%0,%1,%2,%3};"
        : "+f"(d[0]), "+f"(d[1]), "+f"(d[2]), "+f"(d[3])
        : "r"(a[0]), "r"(a[1]), "r"(a[2]), "r"(a[3]), "r"(b[0]), "r"(b[1]));
}

__device__ __forceinline__ void h4store(float4 v, __half* p){
    __half2* P = (__half2*)p;
    P[0] = __floats2half2_rn(v.x, v.y);
    P[1] = __floats2half2_rn(v.z, v.w);
}
__device__ __forceinline__ float4 mixf4(float4 h, float4 hp, float4 m){
    float4 o;
    o.x = h.x*m.x + hp.x*(1.f-m.x);
    o.y = h.y*m.y + hp.y*(1.f-m.y);
    o.z = h.z*m.z + hp.z*(1.f-m.z);
    o.w = h.w*m.w + hp.w*(1.f-m.w);
    return o;
}

// ---------------------------------------------------------------------------
// Fused LayerNorm + token-shift mix. One block per row; the block also
// recomputes LN of the previous row (cheap; memory-bound) so the h
// intermediate never touches DRAM. Reduction op-order matches the original
// ln_kernel exactly (bit-identical h values).
// ---------------------------------------------------------------------------
__device__ __forceinline__ void ln2rows(
    const float* __restrict__ x, size_t row, size_t prow, int tid,
    const float* __restrict__ g, const float* __restrict__ b,
    float4& hv, float4& hp)
{
    float4 vc = ((const float4*)(x + row  * CC))[tid];
    float4 vp = ((const float4*)(x + prow * CC))[tid];
    __shared__ float ws[8], wt[8];

    float s0 = vc.x + vc.y + vc.z + vc.w;
    float s1 = vp.x + vp.y + vp.z + vp.w;
    #pragma unroll
    for (int o = 16; o > 0; o >>= 1) {
        s0 += __shfl_xor_sync(0xffffffffu, s0, o);
        s1 += __shfl_xor_sync(0xffffffffu, s1, o);
    }
    if ((tid & 31) == 0) { ws[tid >> 5] = s0; wt[tid >> 5] = s1; }
    __syncthreads();
    float mu0 = (ws[0]+ws[1]+ws[2]+ws[3]+ws[4]+ws[5]+ws[6]+ws[7]) * (1.0f / CC);
    float mu1 = (wt[0]+wt[1]+wt[2]+wt[3]+wt[4]+wt[5]+wt[6]+wt[7]) * (1.0f / CC);
    __syncthreads();

    float dx0 = vc.x - mu0, dy0 = vc.y - mu0, dz0 = vc.z - mu0, dw0 = vc.w - mu0;
    float dx1 = vp.x - mu1, dy1 = vp.y - mu1, dz1 = vp.z - mu1, dw1 = vp.w - mu1;
    float q0 = dx0*dx0 + dy0*dy0 + dz0*dz0 + dw0*dw0;
    float q1 = dx1*dx1 + dy1*dy1 + dz1*dz1 + dw1*dw1;
    #pragma unroll
    for (int o = 16; o > 0; o >>= 1) {
        q0 += __shfl_xor_sync(0xffffffffu, q0, o);
        q1 += __shfl_xor_sync(0xffffffffu, q1, o);
    }
    if ((tid & 31) == 0) { ws[tid >> 5] = q0; wt[tid >> 5] = q1; }
    __syncthreads();
    float var0 = (ws[0]+ws[1]+ws[2]+ws[3]+ws[4]+ws[5]+ws[6]+ws[7]) * (1.0f / CC);
    float var1 = (wt[0]+wt[1]+wt[2]+wt[3]+wt[4]+wt[5]+wt[6]+wt[7]) * (1.0f / CC);
    float r0 = rsqrtf(var0 + 1e-5f);
    float r1 = rsqrtf(var1 + 1e-5f);

    float4 gv = ((const float4*)g)[tid];
    float4 bv = ((const float4*)b)[tid];
    hv.x = dx0 * r0 * gv.x + bv.x;
    hv.y = dy0 * r0 * gv.y + bv.y;
    hv.z = dz0 * r0 * gv.z + bv.z;
    hv.w = dw0 * r0 * gv.w + bv.w;
    hp.x = dx1 * r1 * gv.x + bv.x;
    hp.y = dy1 * r1 * gv.y + bv.y;
    hp.z = dz1 * r1 * gv.z + bv.z;
    hp.w = dw1 * r1 * gv.w + bv.w;
}

__global__ void __launch_bounds__(256) lnmix3_kernel(
    const float* __restrict__ x, const float* __restrict__ g,
    const float* __restrict__ b,
    const float* __restrict__ mk, const float* __restrict__ mv,
    const float* __restrict__ mr,
    __half* xk, __half* xv, __half* xr)
{
    size_t row = blockIdx.x;
    int tid = threadIdx.x;
    bool first = (row & (TT - 1)) == 0;
    size_t prow = first ? row : row - 1;
    float4 hv, hp;
    ln2rows(x, row, prow, tid, g, b, hv, hp);
    if (first) hp = make_float4(0.f, 0.f, 0.f, 0.f);
    size_t j = row * (CC/4) + tid;
    h4store(mixf4(hv, hp, ((const float4*)mk)[tid]), xk + j*4);
    h4store(mixf4(hv, hp, ((const float4*)mv)[tid]), xv + j*4);
    h4store(mixf4(hv, hp, ((const float4*)mr)[tid]), xr + j*4);
}

__global__ void __launch_bounds__(256) lnmix2_kernel(
    const float* __restrict__ x, const float* __restrict__ g,
    const float* __restrict__ b,
    const float* __restrict__ mk, const float* __restrict__ mr,
    __half* ck, __half* cr)
{
    size_t row = blockIdx.x;
    int tid = threadIdx.x;
    bool first = (row & (TT - 1)) == 0;
    size_t prow = first ? row : row - 1;
    float4 hv, hp;
    ln2rows(x, row, prow, tid, g, b, hv, hp);
    if (first) hp = make_float4(0.f, 0.f, 0.f, 0.f);
    size_t j = row * (CC/4) + tid;
    h4store(mixf4(hv, hp, ((const float4*)mk)[tid]), ck + j*4);
    h4store(mixf4(hv, hp, ((const float4*)mr)[tid]), cr + j*4);
}

// ---------------------------------------------------------------------------
// WKV chunked scan, single fused kernel.
// Block = one (batch, 16-channel group): 256 threads = 16 chunks x 16 chans.
// Phase 1: per-chunk pp_loc (scan k) -> smem.
// Fold:    pp_in = LSE-prefix over previous chunks (computed once).
// Phase 2: replay pp path with true pp_in, emit (alpha, beta) -> smem.
// Fold:    aa_in = affine-prefix over (alpha, beta).
// Phase 3: replay chunk exactly as reference from (aa_in, pp_in), write
//          out = x + r*y.  Identical op sequences to the proven 3-kernel
//          version; only the aggregate storage moved to smem.
// ---------------------------------------------------------------------------
__global__ void __launch_bounds__(256) wkv_fused(
    const float* __restrict__ kp, const float* __restrict__ vp,
    const float* __restrict__ rp, const float* __restrict__ xp,
    const float* __restrict__ wdec, const float* __restrict__ ufst,
    float* __restrict__ out)
{
    __shared__ float spp[NCH][16];
    __shared__ float sal[NCH][16];
    __shared__ float sbe[NCH][16];

    int tid = threadIdx.x;
    int cl = tid & 15;          // channel within group
    int ch = tid >> 4;          // chunk index
    int b  = blockIdx.x >> 6;
    int c  = (blockIdx.x & 63) * 16 + cl;
    float w = wdec[c], u = ufst[c];
    const size_t base = ((size_t)b * TT + (size_t)ch * CHL) * CC + c;

    // ---- phase 1: pp_loc per chunk
    {
        float pp = -1e38f;
        size_t idx = base;
        #pragma unroll 2
        for (int t = 0; t < CHL; t++, idx += CC) {
            float kk = kp[idx];
            float pw = pp + w, wk = w + kk;
            float p2 = fmaxf(pw, wk);
            pp = p2 + __logf(__expf(pw - p2) + __expf(wk - p2));
        }
        spp[ch][cl] = pp;
    }
    __syncthreads();

    // ---- fold pp_in (once; reused by phases 2 and 3)
    float Lw = (float)CHL * w;
    float pin = -1e38f;
    for (int j = 0; j < ch; j++) {
        float a  = pin + Lw;
        float pl = spp[j][cl];
        float m  = fmaxf(a, pl);
        pin = m + __logf(__expf(a - m) + __expf(pl - m));
    }

    // ---- phase 2: (alpha, beta) with true incoming pp
    {
        float pp = pin;
        float alpha = 1.0f, beta = 0.0f;
        size_t idx = base;
        #pragma unroll 2
        for (int t = 0; t < CHL; t++, idx += CC) {
            float kk = kp[idx], vv = vp[idx];
            float pw = pp + w, wk = w + kk;
            float p2 = fmaxf(pw, wk);
            float e1u = __expf(pw - p2);
            float e2u = __expf(wk - p2);
            alpha *= e1u;
            beta = e1u * beta + e2u * vv;
            pp = p2 + __logf(e1u + e2u);
        }
        sal[ch][cl] = alpha;
        sbe[ch][cl] = beta;
    }
    __syncthreads();

    // ---- fold aa_in
    float aa = 0.0f;
    for (int j = 0; j < ch; j++)
        aa = sal[j][cl] * aa + sbe[j][cl];

    // ---- phase 3: exact reference replay + fused output
    {
        float pp = pin;
        size_t idx = base;
        #pragma unroll 2
        for (int t = 0; t < CHL; t++, idx += CC) {
            float kk = kp[idx];
            float vv = vp[idx];
            float rr = rp[idx];
            float xx = xp[idx];
            float uk = u + kk;
            float p  = fmaxf(pp, uk);
            float e1 = __expf(pp - p);
            float e2 = __expf(uk - p);
            float y  = (e1 * aa + e2 * vv) / (e1 + e2);
            out[idx] = xx + rr * y;
            float pw = pp + w;
            float wk = w + kk;
            float p2 = fmaxf(pw, wk);
            float e1u = __expf(pw - p2);
            float e2u = __expf(wk - p2);
            aa = e1u * aa + e2u * vv;
            pp = p2 + __logf(e1u + e2u);
        }
    }
}

// ---------------------------------------------------------------------------
// Weight transpose + fp16 RN: src[R,Ccols] fp32 -> dst[Ccols,R] fp16
// ---------------------------------------------------------------------------
__global__ void __launch_bounds__(256) thalf_kernel(
    const float* __restrict__ src, __half* __restrict__ dst, int R, int Ccols)
{
    __shared__ float t[32][33];
    int r0 = blockIdx.y * 32, c0 = blockIdx.x * 32;
    int tx = threadIdx.x, ty = threadIdx.y;
    #pragma unroll
    for (int j = 0; j < 32; j += 8)
        t[ty + j][tx] = src[(size_t)(r0 + ty + j) * Ccols + c0 + tx];
    __syncthreads();
    #pragma unroll
    for (int j = 0; j < 32; j += 8)
        dst[(size_t)(c0 + ty + j) * R + r0 + tx] = __float2half_rn(t[tx][ty + j]);
}

// ---------------------------------------------------------------------------
// fp16 single-pass GEMM core with cross-stage fragment double-buffering
// (R15 proven). C[M,N] = epi(A[M,K] @ Bt[N,K]^T), fp32 accum.
// CTA tile 256x128, k-step 16, 4 committed cp.async stages.
// phys(row, c) = (row>>3)*256 + ((c<<3 | (row&7))<<4), c = k-half (0/1).
// ---------------------------------------------------------------------------
#define CTM 256
#define CTN 128
#define ST_A 8192
#define STAGE_BYTES 12288
#define GSMEM (STAGE_BYTES*4)   // 49152

#define EPI_NONE 0
#define EPI_SIGMOID 1
#define EPI_RELUSQ 2
#define EPI_RESID 3

template<int EPI>
__device__ __forceinline__ void gemm_core(
    const __half* __restrict__ A, const __half* __restrict__ Bt,
    int K, int m0, int n0B,
    float* __restrict__ outF, const float* __restrict__ resid,
    const float* __restrict__ gate,
    __half* __restrict__ outH, int Nout, int n0o)
{
    extern __shared__ char smem[];
    const uint32_t sbase = smem_u32(smem);
    const int tid = threadIdx.x;
    const int lane = tid & 31, wid = tid >> 5;
    const int wm = wid & 3, wn = wid >> 2;
    const int NS = K >> 4;

    auto load_stage = [&](int s, int buf){
        const int k0 = s << 4;
        uint32_t st = sbase + (uint32_t)buf * STAGE_BYTES;
        #pragma unroll
        for (int l = 0; l < 2; l++) {
            int chk = l*256 + tid;                  // 0..511
            int row = chk >> 1, c = chk & 1;
            uint32_t d = (uint32_t)((row>>3)<<8) | (uint32_t)((((c<<3)|(row&7)))<<4);
            cp16(st + d, A + (size_t)(m0+row)*K + k0 + c*8);
        }
        {
            int row = tid >> 1, c = tid & 1;        // 0..255 chunks
            uint32_t d = (uint32_t)((row>>3)<<8) | (uint32_t)((((c<<3)|(row&7)))<<4);
            cp16(st + ST_A + d, Bt + (size_t)(n0B+row)*K + k0 + c*8);
        }
    };

    const int rl = lane & 15, chh = lane >> 4;
    const uint32_t bpart = (uint32_t)(((rl>>3)<<8) | (((chh<<3)|(rl&7))<<4));

    auto ldsm_stage = [&](int buf, uint32_t a[4][4], uint32_t b[8][2]){
        uint32_t stA = sbase + (uint32_t)buf * STAGE_BYTES;
        uint32_t stB = stA + ST_A;
        #pragma unroll
        for (int mi = 0; mi < 4; mi++) {
            uint32_t ad = stA + (uint32_t)((wm*8 + mi*2) << 8) + bpart;
            LDSM4(a[mi][0], a[mi][1], a[mi][2], a[mi][3], ad);
        }
        #pragma unroll
        for (int g = 0; g < 4; g++) {
            uint32_t bd = stB + (uint32_t)((wn*8 + g*2) << 8) + bpart;
            uint32_t r0, r1, r2, r3;
            LDSM4(r0, r1, r2, r3, bd);
            b[2*g][0] = r0;   b[2*g][1] = r2;
            b[2*g+1][0] = r1; b[2*g+1][1] = r3;
        }
    };

    float acc[4][8][4];
    #pragma unroll
    for (int mi = 0; mi < 4; mi++)
        #pragma unroll
        for (int ni = 0; ni < 8; ni++)
            #pragma unroll
            for (int c = 0; c < 4; c++) acc[mi][ni][c] = 0.0f;

    load_stage(0, 0); CP_COMMIT();
    load_stage(1, 1); CP_COMMIT();
    load_stage(2, 2); CP_COMMIT();
    load_stage(3, 3); CP_COMMIT();

    uint32_t af[2][4][4], bf[2][8][2];
    CP_WAIT3();
    __syncthreads();
    ldsm_stage(0, af[0], bf[0]);

    #pragma unroll 2
    for (int s = 0; s < NS; s++) {
        const int pc = s & 1, pn = pc ^ 1;
        CP_WAIT2();            // groups complete in order -> stage s+1 arrived
        __syncthreads();       // cross-thread visibility; buf s&3 fully consumed
        if (s + 4 < NS) load_stage(s + 4, s & 3);
        CP_COMMIT();
        if (s + 1 < NS) ldsm_stage((s + 1) & 3, af[pn], bf[pn]);
        #pragma unroll
        for (int mi = 0; mi < 4; mi++)
            #pragma unroll
            for (int ni = 0; ni < 8; ni++)
                mma16816(acc[mi][ni], af[pc][mi], bf[pc][ni]);
    }

    // ---- epilogue
    #pragma unroll
    for (int mi = 0; mi < 4; mi++) {
        int r0 = m0 + wm*64 + mi*16 + (lane >> 2);
        #pragma unroll
        for (int ni = 0; ni < 8; ni++) {
            int c0 = n0o + wn*64 + ni*8 + (lane & 3)*2;
            float v0 = acc[mi][ni][0], v1 = acc[mi][ni][1];
            float v2 = acc[mi][ni][2], v3 = acc[mi][ni][3];
            size_t i0 = (size_t)r0 * Nout + c0;
            size_t i1 = (size_t)(r0 + 8) * Nout + c0;
            if (EPI == EPI_SIGMOID) {
                v0 = 1.f/(1.f+__expf(-v0)); v1 = 1.f/(1.f+__expf(-v1));
                v2 = 1.f/(1.f+__expf(-v2)); v3 = 1.f/(1.f+__expf(-v3));
            } else if (EPI == EPI_RELUSQ) {
                v0 = fmaxf(v0,0.f); v1 = fmaxf(v1,0.f);
                v2 = fmaxf(v2,0.f); v3 = fmaxf(v3,0.f);
                *(__half2*)(outH + i0) = __floats2half2_rn(v0*v0, v1*v1);
                *(__half2*)(outH + i1) = __floats2half2_rn(v2*v2, v3*v3);
                continue;
            }
            if (EPI == EPI_RESID) {
                float2 rz0 = *(const float2*)(resid + i0);
                float2 rz1 = *(const float2*)(resid + i1);
                float2 gz0 = *(const float2*)(gate  + i0);
                float2 gz1 = *(const float2*)(gate  + i1);
                v0 = rz0.x + gz0.x*v0; v1 = rz0.y + gz0.y*v1;
                v2 = rz1.x + gz1.x*v2; v3 = rz1.y + gz1.y*v3;
            }
            *(float2*)(outF + i0) = make_float2(v0, v1);
            *(float2*)(outF + i1) = make_float2(v2, v3);
        }
    }
}

// Fused k|v|r GEMM: N-blocks 0-7 -> k, 8-15 -> v, 16-23 -> sigmoid r
__global__ void __launch_bounds__(256, 1) gemm_kvr(
    const __half* xk, const __half* xv, const __half* xr,
    const __half* Bt, float* outk, float* outv, float* outr)
{
    int seg = blockIdx.x >> 3;
    int m0  = blockIdx.y * CTM;
    int n0B = blockIdx.x * CTN;
    int n0o = (blockIdx.x & 7) * CTN;
    const __half* Aa = (seg == 0) ? xk : (seg == 1) ? xv : xr;
    float* o = (seg == 0) ? outk : (seg == 1) ? outv : outr;
    if (seg == 2)
        gemm_core<EPI_SIGMOID>(Aa, Bt, CC, m0, n0B, o, nullptr, nullptr, nullptr, CC, n0o);
    else
        gemm_core<EPI_NONE>(Aa, Bt, CC, m0, n0B, o, nullptr, nullptr, nullptr, CC, n0o);
}

// Fused kk|s GEMM: N-blocks 0-31 -> relu^2 kk (fp16), 32-39 -> sigmoid s
__global__ void __launch_bounds__(256, 1) gemm_cks(
    const __half* ck, const __half* cr, const __half* Bt,
    __half* kk, float* outs)
{
    int bx = blockIdx.x;
    int m0 = blockIdx.y * CTM;
    int n0B = bx * CTN;
    if (bx < 32)
        gemm_core<EPI_RELUSQ>(ck, Bt, CC, m0, n0B, nullptr, nullptr, nullptr, kk, 4*CC, bx*CTN);
    else
        gemm_core<EPI_SIGMOID>(cr, Bt, CC, m0, n0B, outs, nullptr, nullptr, nullptr, CC, (bx-32)*CTN);
}

// Final GEMM: out = x2 + s * (kk @ w_cv), K = 4096
__global__ void __launch_bounds__(256, 1) gemm_out(
    const __half* kk, const __half* Bt,
    float* out, const float* x2, const float* sg)
{
    int m0 = blockIdx.y * CTM;
    int n0 = blockIdx.x * CTN;
    gemm_core<EPI_RESID>(kk, Bt, 4*CC, m0, n0, out, x2, sg, nullptr, CC, n0);
}

// ---------------------------------------------------------------------------
// Host launcher
// ---------------------------------------------------------------------------
template<typename T>
static T* symaddr(const void* sym)
{
    void* p = nullptr;
    cudaGetSymbolAddress(&p, sym);
    return (T*)p;
}

extern "C" void kernel_launch(void* const* d_in, const int* in_sizes, int n_in,
                              void* d_out, int out_size)
{
    const float* x      = (const float*)d_in[0];
    const float* tdecay = (const float*)d_in[1];
    const float* tfirst = (const float*)d_in[2];
    const float* w_tk   = (const float*)d_in[3];
    const float* w_tv   = (const float*)d_in[4];
    const float* w_tr   = (const float*)d_in[5];
    const float* w_ck   = (const float*)d_in[6];
    const float* w_cv   = (const float*)d_in[7];
    const float* w_cr   = (const float*)d_in[8];
    const float* ln1_g  = (const float*)d_in[9];
    const float* ln1_b  = (const float*)d_in[10];
    const float* ln2_g  = (const float*)d_in[11];
    const float* ln2_b  = (const float*)d_in[12];
    const float* mix_k  = (const float*)d_in[13];
    const float* mix_v  = (const float*)d_in[14];
    const float* mix_r  = (const float*)d_in[15];
    const float* cmix_k = (const float*)d_in[16];
    const float* cmix_r = (const float*)d_in[17];
    float* out = (float*)d_out;

    float* k   = symaddr<float>(g_k);
    float* v   = symaddr<float>(g_v);
    float* r   = symaddr<float>(g_r);
    float* x2  = symaddr<float>(g_x2);
    float* s   = symaddr<float>(g_s);
    __half* xk = symaddr<__half>(g_xk);
    __half* xv = symaddr<__half>(g_xv);
    __half* xr = symaddr<__half>(g_xr);
    __half* ck = symaddr<__half>(g_ck);
    __half* cr = symaddr<__half>(g_cr);
    __half* kk = symaddr<__half>(g_kk);
    __half* wkvr = symaddr<__half>(g_wkvr);
    __half* wcks = symaddr<__half>(g_wcks);
    __half* wcv  = symaddr<__half>(g_wcv);

    cudaFuncSetAttribute((const void*)gemm_kvr, cudaFuncAttributeMaxDynamicSharedMemorySize, GSMEM);
    cudaFuncSetAttribute((const void*)gemm_cks, cudaFuncAttributeMaxDynamicSharedMemorySize, GSMEM);
    cudaFuncSetAttribute((const void*)gemm_out, cudaFuncAttributeMaxDynamicSharedMemorySize, GSMEM);

    const int M = MROWS;
    dim3 tb(32, 8);

    // 0-2) transpose+fp16 time-mix weights into concat buffer [3072,1024]
    thalf_kernel<<<dim3(CC/32, CC/32), tb>>>(w_tk, wkvr,           CC, CC);
    thalf_kernel<<<dim3(CC/32, CC/32), tb>>>(w_tv, wkvr + CC*CC,   CC, CC);
    thalf_kernel<<<dim3(CC/32, CC/32), tb>>>(w_tr, wkvr + 2*CC*CC, CC, CC);

    // 3) fused LN1 + token-shift mixes (fp16), no h round-trip
    lnmix3_kernel<<<M, 256>>>(x, ln1_g, ln1_b, mix_k, mix_v, mix_r, xk, xv, xr);

    // 4) fused k|v|r GEMM
    gemm_kvr<<<dim3(24, M/CTM), 256, GSMEM>>>(xk, xv, xr, wkvr, k, v, r);

    // 5) x2 = x + r * WKV(k, v)  — single fused chunked scan
    wkv_fused<<<MB * (CC/16), 256>>>(k, v, r, x, tdecay, tfirst, x2);

    // 6) fused LN2 + channel mixes
    lnmix2_kernel<<<M, 256>>>(x2, ln2_g, ln2_b, cmix_k, cmix_r, ck, cr);

    // 7-9) transpose+fp16 channel weights: concat [5120,1024] and [1024,4096]
    thalf_kernel<<<dim3(4*CC/32, CC/32), tb>>>(w_ck, wcks,           CC, 4*CC);
    thalf_kernel<<<dim3(CC/32, CC/32),   tb>>>(w_cr, wcks + 4*CC*CC, CC, CC);
    thalf_kernel<<<dim3(CC/32, 4*CC/32), tb>>>(w_cv, wcv,            4*CC, CC);

    // 10) fused kk|s GEMM: kk = relu(ck@w_ck)^2 (fp16), s = sigmoid(cr@w_cr)
    gemm_cks<<<dim3(40, M/CTM), 256, GSMEM>>>(ck, cr, wcks, kk, s);

    // 11) out = x2 + s * (kk @ w_cv), K = 4096
    gemm_out<<<dim3(8, M/CTM), 256, GSMEM>>>(kk, wcv, out, x2, s);
}